// round 1
// baseline (speedup 1.0000x reference)
#include <cuda_runtime.h>
#include <cuda_fp16.h>
#include <mma.h>

using namespace nvcuda;

// Problem dims (fixed by the dataset)
#define M_DIM 8192   // B*S = 4*2048
#define N_DIM 4096   // OUT_F
#define K_DIM 4096   // IN_F

// GEMM tiling
#define BM 128
#define BN 128
#define BK 32
#define LDS 48      // padded smem leading dim in halves (96B rows: 32B-aligned for wmma)

// Scratch: dequantized weights + converted activations (no cudaMalloc allowed)
__device__ __half g_W[(size_t)N_DIM * K_DIM];   // 32 MB
__device__ __half g_X[(size_t)M_DIM * K_DIM];   // 64 MB

// ---------------------------------------------------------------------------
// Kernel 1: dequantize W[o,i] = lut[idx[o,i]] * scale[o]  -> fp16
// Vectorized 4 codes / thread. K_DIM % 4 == 0 so all 4 share one row.
// ---------------------------------------------------------------------------
__global__ void dequant_w_kernel(const int* __restrict__ idx,
                                 const float* __restrict__ scale,
                                 const float* __restrict__ lut) {
    size_t t = (size_t)blockIdx.x * blockDim.x + threadIdx.x;
    size_t base = t * 4;
    if (base >= (size_t)N_DIM * K_DIM) return;
    int row = (int)(base / K_DIM);
    float s = scale[row];
    int4 code = *reinterpret_cast<const int4*>(idx + base);
    float w0 = lut[code.x] * s;
    float w1 = lut[code.y] * s;
    float w2 = lut[code.z] * s;
    float w3 = lut[code.w] * s;
    __half2 h0 = __floats2half2_rn(w0, w1);
    __half2 h1 = __floats2half2_rn(w2, w3);
    *reinterpret_cast<__half2*>(g_W + base)     = h0;
    *reinterpret_cast<__half2*>(g_W + base + 2) = h1;
}

// ---------------------------------------------------------------------------
// Kernel 2: convert x fp32 -> fp16 (vectorized float4 -> 4 halves)
// ---------------------------------------------------------------------------
__global__ void convert_x_kernel(const float* __restrict__ x) {
    size_t t = (size_t)blockIdx.x * blockDim.x + threadIdx.x;
    size_t base = t * 4;
    if (base >= (size_t)M_DIM * K_DIM) return;
    float4 v = *reinterpret_cast<const float4*>(x + base);
    __half2 h0 = __floats2half2_rn(v.x, v.y);
    __half2 h1 = __floats2half2_rn(v.z, v.w);
    *reinterpret_cast<__half2*>(g_X + base)     = h0;
    *reinterpret_cast<__half2*>(g_X + base + 2) = h1;
}

// ---------------------------------------------------------------------------
// Kernel 3: GEMM  out[m,n] = sum_k X[m,k] * W[n,k]   (fp16 in, fp32 acc/out)
// CTA 128x128x32, 256 threads, 8 warps in 2(M) x 4(N) layout,
// warp tile 64x32 = 4x2 wmma 16x16x16 fragments.
// ---------------------------------------------------------------------------
__global__ void __launch_bounds__(256, 2)
gemm_kernel(float* __restrict__ out) {
    __shared__ __half As[BM * LDS];
    __shared__ __half Bs[BN * LDS];

    const int m0 = blockIdx.y * BM;
    const int n0 = blockIdx.x * BN;
    const int tid = threadIdx.x;
    const int warp = tid >> 5;
    const int wm = warp >> 2;   // 0..1 : 64-row slab
    const int wn = warp & 3;    // 0..3 : 32-col slab

    wmma::fragment<wmma::accumulator, 16, 16, 16, float> c[4][2];
    #pragma unroll
    for (int i = 0; i < 4; i++)
        #pragma unroll
        for (int j = 0; j < 2; j++)
            wmma::fill_fragment(c[i][j], 0.0f);

    for (int k0 = 0; k0 < K_DIM; k0 += BK) {
        // Stage A (X tile) and B (W tile): 128 rows x 32 halves each.
        // 512 uint4 chunks per tile; 2 chunks per thread, coalesced.
        #pragma unroll
        for (int cc = 0; cc < 2; cc++) {
            int chunk = cc * 256 + tid;        // 0..511
            int row = chunk >> 2;              // 0..127
            int kc  = (chunk & 3) * 8;         // 0,8,16,24
            *reinterpret_cast<uint4*>(As + row * LDS + kc) =
                *reinterpret_cast<const uint4*>(g_X + (size_t)(m0 + row) * K_DIM + k0 + kc);
            *reinterpret_cast<uint4*>(Bs + row * LDS + kc) =
                *reinterpret_cast<const uint4*>(g_W + (size_t)(n0 + row) * K_DIM + k0 + kc);
        }
        __syncthreads();

        #pragma unroll
        for (int kk = 0; kk < BK; kk += 16) {
            wmma::fragment<wmma::matrix_a, 16, 16, 16, __half, wmma::row_major> a[4];
            wmma::fragment<wmma::matrix_b, 16, 16, 16, __half, wmma::col_major> b[2];
            #pragma unroll
            for (int i = 0; i < 4; i++)
                wmma::load_matrix_sync(a[i], As + (wm * 64 + i * 16) * LDS + kk, LDS);
            #pragma unroll
            for (int j = 0; j < 2; j++)
                wmma::load_matrix_sync(b[j], Bs + (wn * 32 + j * 16) * LDS + kk, LDS);
            #pragma unroll
            for (int i = 0; i < 4; i++)
                #pragma unroll
                for (int j = 0; j < 2; j++)
                    wmma::mma_sync(c[i][j], a[i], b[j], c[i][j]);
        }
        __syncthreads();
    }

    #pragma unroll
    for (int i = 0; i < 4; i++)
        #pragma unroll
        for (int j = 0; j < 2; j++)
            wmma::store_matrix_sync(
                out + (size_t)(m0 + wm * 64 + i * 16) * N_DIM + (n0 + wn * 32 + j * 16),
                c[i][j], N_DIM, wmma::mem_row_major);
}

// ---------------------------------------------------------------------------
// Entry point. Inputs (metadata order): x f32, grid_indices i32, scale f32, lut f32
// Output: float32 [B,S,OUT_F] = [8192, 4096] row-major.
// ---------------------------------------------------------------------------
extern "C" void kernel_launch(void* const* d_in, const int* in_sizes, int n_in,
                              void* d_out, int out_size) {
    const float* x     = (const float*)d_in[0];
    const int*   idx   = (const int*)  d_in[1];
    const float* scale = (const float*)d_in[2];
    const float* lut   = (const float*)d_in[3];
    float* out = (float*)d_out;

    {
        size_t elems = (size_t)N_DIM * K_DIM / 4;   // 4 codes per thread
        int threads = 256;
        int blocks = (int)((elems + threads - 1) / threads);
        dequant_w_kernel<<<blocks, threads>>>(idx, scale, lut);
    }
    {
        size_t elems = (size_t)M_DIM * K_DIM / 4;
        int threads = 256;
        int blocks = (int)((elems + threads - 1) / threads);
        convert_x_kernel<<<blocks, threads>>>(x);
    }
    {
        dim3 grid(N_DIM / BN, M_DIM / BM);   // 32 x 64
        gemm_kernel<<<grid, 256>>>(out);
    }
}

// round 3
// speedup vs baseline: 1.8048x; 1.8048x over previous
#include <cuda_runtime.h>
#include <cuda_fp16.h>
#include <cstdint>

// Problem dims (fixed by the dataset)
#define M_DIM 8192   // B*S
#define N_DIM 4096   // OUT_F
#define K_DIM 4096   // IN_F

// GEMM tiling
#define BM 128
#define BN 128
#define BK 64                      // 64 halves = 128B rows (SW128 atom)
#define NSTAGES 4
#define KSTEPS (K_DIM / BK)        // 64

#define A_STAGE_BYTES (BM * 128)   // 16 KB
#define B_STAGE_BYTES (BN * 128)   // 16 KB
#define STAGE_BYTES   (A_STAGE_BYTES + B_STAGE_BYTES)   // 32 KB
#define SMEM_TOTAL    (NSTAGES * STAGE_BYTES)           // 128 KB

// Scratch (no cudaMalloc allowed)
__device__ __half g_W[(size_t)N_DIM * K_DIM];   // 32 MB dequantized weights
__device__ __half g_X[(size_t)M_DIM * K_DIM];   // 64 MB fp16 activations

// ---------------------------------------------------------------------------
// helpers
// ---------------------------------------------------------------------------
static __device__ __forceinline__ uint32_t s2u(const void* p) {
    uint32_t a;
    asm("{ .reg .u64 t; cvta.to.shared.u64 t, %1; cvt.u32.u64 %0, t; }"
        : "=r"(a) : "l"(p));
    return a;
}

static __device__ __forceinline__ void cp_async16(uint32_t dst, const void* src) {
    asm volatile("cp.async.cg.shared.global [%0], [%1], 16;"
                 :: "r"(dst), "l"(src) : "memory");
}
#define CP_COMMIT() asm volatile("cp.async.commit_group;" ::: "memory")
#define CP_WAIT2()  asm volatile("cp.async.wait_group 2;" ::: "memory")
#define CP_WAIT0()  asm volatile("cp.async.wait_group 0;" ::: "memory")

#define LDSM_X4(r0, r1, r2, r3, a) \
    asm volatile("ldmatrix.sync.aligned.m8n8.x4.shared.b16 {%0,%1,%2,%3}, [%4];" \
                 : "=r"(r0), "=r"(r1), "=r"(r2), "=r"(r3) : "r"(a))

static __device__ __forceinline__ void mma16816(float* c, const uint32_t* a,
                                                const uint32_t* b) {
    asm volatile(
        "mma.sync.aligned.m16n8k16.row.col.f32.f16.f16.f32 "
        "{%0,%1,%2,%3}, {%4,%5,%6,%7}, {%8,%9}, {%0,%1,%2,%3};"
        : "+f"(c[0]), "+f"(c[1]), "+f"(c[2]), "+f"(c[3])
        : "r"(a[0]), "r"(a[1]), "r"(a[2]), "r"(a[3]), "r"(b[0]), "r"(b[1]));
}

// ---------------------------------------------------------------------------
// Kernel 1: dequantize W[o,i] = lut[idx[o,i]] * scale[o]  -> fp16
// ---------------------------------------------------------------------------
__global__ void dequant_w_kernel(const int* __restrict__ idx,
                                 const float* __restrict__ scale,
                                 const float* __restrict__ lut) {
    size_t t = (size_t)blockIdx.x * blockDim.x + threadIdx.x;
    size_t base = t * 4;
    if (base >= (size_t)N_DIM * K_DIM) return;
    int row = (int)(base / K_DIM);
    float s = scale[row];
    int4 code = *reinterpret_cast<const int4*>(idx + base);
    *reinterpret_cast<__half2*>(g_W + base) =
        __floats2half2_rn(lut[code.x] * s, lut[code.y] * s);
    *reinterpret_cast<__half2*>(g_W + base + 2) =
        __floats2half2_rn(lut[code.z] * s, lut[code.w] * s);
}

// ---------------------------------------------------------------------------
// Kernel 2: convert x fp32 -> fp16
// ---------------------------------------------------------------------------
__global__ void convert_x_kernel(const float* __restrict__ x) {
    size_t t = (size_t)blockIdx.x * blockDim.x + threadIdx.x;
    size_t base = t * 4;
    if (base >= (size_t)M_DIM * K_DIM) return;
    float4 v = *reinterpret_cast<const float4*>(x + base);
    *reinterpret_cast<__half2*>(g_X + base)     = __floats2half2_rn(v.x, v.y);
    *reinterpret_cast<__half2*>(g_X + base + 2) = __floats2half2_rn(v.z, v.w);
}

// ---------------------------------------------------------------------------
// Kernel 3: HMMA GEMM. CTA 128x128, BK=64, 8 warps (2m x 4n), warp tile 64x32.
// 4-stage cp.async pipeline, SW128-swizzled smem, ldmatrix.x4, mma.sync 16816.
//   out[m,n] = sum_k X[m,k] * W[n,k]
// ---------------------------------------------------------------------------
__device__ __forceinline__ void load_stage(int tid, uint32_t sb, int s, int kstep,
                                           const char* Ag, const char* Bg) {
    // stage tile: 128 rows x 8 chunks of 16B, swizzle: chunk ^= row&7
    uint32_t SA = sb + s * STAGE_BYTES;
    uint32_t SB = SA + A_STAGE_BYTES;
    const size_t krow = (size_t)K_DIM * 2;           // row stride bytes
    const char* Akp = Ag + (size_t)kstep * 128;      // +kstep*64 halves
    const char* Bkp = Bg + (size_t)kstep * 128;
    #pragma unroll
    for (int j = 0; j < 4; j++) {
        int cid = tid + 256 * j;                     // 0..1023
        int row = cid >> 3;
        int c   = cid & 7;
        uint32_t sw = (uint32_t)(row * 128 + ((c ^ (row & 7)) * 16));
        cp_async16(SA + sw, Akp + (size_t)row * krow + c * 16);
        cp_async16(SB + sw, Bkp + (size_t)row * krow + c * 16);
    }
}

__global__ void __launch_bounds__(256, 1)
gemm_hmma_kernel(float* __restrict__ out) {
    extern __shared__ __align__(1024) char smem[];
    const uint32_t sb = s2u(smem);
    const int tid = threadIdx.x;
    const int wid = tid >> 5;
    const int lid = tid & 31;
    const int wm = wid & 1;        // 0..1 : 64-row slab
    const int wn = wid >> 1;       // 0..3 : 32-col slab
    const int m0 = blockIdx.y * BM;
    const int n0 = blockIdx.x * BN;

    const char* Ag = (const char*)(g_X + (size_t)m0 * K_DIM);
    const char* Bg = (const char*)(g_W + (size_t)n0 * K_DIM);

    // per-lane ldmatrix address components (stage-relative)
    // A: lanes: row = wm*64 + i*16 + (l&15), chunk = 2q + (l>>4), xor (l&7)
    // B: lanes: row = wn*32 + j2*16 + (l&7) + ((l>>4)&1)*8,
    //           chunk = 2q + ((l>>3)&1), xor (l&7)
    uint32_t a_rowoff[4], b_rowoff[2];
    #pragma unroll
    for (int i = 0; i < 4; i++)
        a_rowoff[i] = (uint32_t)((wm * 64 + i * 16 + (lid & 15)) * 128);
    #pragma unroll
    for (int j2 = 0; j2 < 2; j2++)
        b_rowoff[j2] = (uint32_t)((wn * 32 + j2 * 16 + (lid & 7) +
                                   ((lid >> 4) & 1) * 8) * 128);
    uint32_t a_ch[4], b_ch[4];
    #pragma unroll
    for (int q = 0; q < 4; q++) {
        a_ch[q] = (uint32_t)((((2 * q + (lid >> 4)) ^ (lid & 7)) * 16));
        b_ch[q] = (uint32_t)((((2 * q + ((lid >> 3) & 1)) ^ (lid & 7)) * 16));
    }

    float acc[4][4][4];
    #pragma unroll
    for (int i = 0; i < 4; i++)
        #pragma unroll
        for (int j = 0; j < 4; j++)
            #pragma unroll
            for (int r = 0; r < 4; r++)
                acc[i][j][r] = 0.0f;

    // Prologue: fill stages 0..2
    #pragma unroll
    for (int s = 0; s < NSTAGES - 1; s++) {
        load_stage(tid, sb, s, s, Ag, Bg);
        CP_COMMIT();
    }

    uint32_t a_frag[2][4][4];
    uint32_t b_frag[2][2][4];

    for (int i = 0; i < KSTEPS; i++) {
        CP_WAIT2();
        __syncthreads();
        if (i + NSTAGES - 1 < KSTEPS)
            load_stage(tid, sb, (i + NSTAGES - 1) & (NSTAGES - 1),
                       i + NSTAGES - 1, Ag, Bg);
        CP_COMMIT();

        const uint32_t SA = sb + (i & (NSTAGES - 1)) * STAGE_BYTES;
        const uint32_t SB = SA + A_STAGE_BYTES;

        // prefetch q=0 fragments
        #pragma unroll
        for (int t4 = 0; t4 < 4; t4++)
            LDSM_X4(a_frag[0][t4][0], a_frag[0][t4][1],
                    a_frag[0][t4][2], a_frag[0][t4][3],
                    SA + a_rowoff[t4] + a_ch[0]);
        #pragma unroll
        for (int j2 = 0; j2 < 2; j2++)
            LDSM_X4(b_frag[0][j2][0], b_frag[0][j2][1],
                    b_frag[0][j2][2], b_frag[0][j2][3],
                    SB + b_rowoff[j2] + b_ch[0]);

        #pragma unroll
        for (int q = 0; q < 4; q++) {
            const int cur = q & 1, nxt = cur ^ 1;
            if (q < 3) {
                #pragma unroll
                for (int t4 = 0; t4 < 4; t4++)
                    LDSM_X4(a_frag[nxt][t4][0], a_frag[nxt][t4][1],
                            a_frag[nxt][t4][2], a_frag[nxt][t4][3],
                            SA + a_rowoff[t4] + a_ch[q + 1]);
                #pragma unroll
                for (int j2 = 0; j2 < 2; j2++)
                    LDSM_X4(b_frag[nxt][j2][0], b_frag[nxt][j2][1],
                            b_frag[nxt][j2][2], b_frag[nxt][j2][3],
                            SB + b_rowoff[j2] + b_ch[q + 1]);
            }
            #pragma unroll
            for (int t4 = 0; t4 < 4; t4++)
                #pragma unroll
                for (int j = 0; j < 4; j++)
                    mma16816(acc[t4][j], a_frag[cur][t4],
                             &b_frag[cur][j >> 1][(j & 1) * 2]);
        }
    }
    CP_WAIT0();

    // Epilogue: c{0,1} -> (row g, col 2tc), c{2,3} -> (row g+8, col 2tc)
    const int g  = lid >> 2;
    const int tc = lid & 3;
    float* Cb = out + (size_t)(m0 + wm * 64) * N_DIM + n0 + wn * 32;
    #pragma unroll
    for (int t4 = 0; t4 < 4; t4++) {
        #pragma unroll
        for (int j = 0; j < 4; j++) {
            float* p0 = Cb + (size_t)(t4 * 16 + g) * N_DIM + j * 8 + tc * 2;
            float* p1 = p0 + 8 * N_DIM;
            *reinterpret_cast<float2*>(p0) = make_float2(acc[t4][j][0], acc[t4][j][1]);
            *reinterpret_cast<float2*>(p1) = make_float2(acc[t4][j][2], acc[t4][j][3]);
        }
    }
}

// ---------------------------------------------------------------------------
// Entry point. Inputs: x f32, grid_indices i32, scale f32, lut f32.
// Output: float32 [8192, 4096].
// ---------------------------------------------------------------------------
extern "C" void kernel_launch(void* const* d_in, const int* in_sizes, int n_in,
                              void* d_out, int out_size) {
    const float* x     = (const float*)d_in[0];
    const int*   idx   = (const int*)  d_in[1];
    const float* scale = (const float*)d_in[2];
    const float* lut   = (const float*)d_in[3];
    float* out = (float*)d_out;

    {
        size_t elems = (size_t)N_DIM * K_DIM / 4;
        dequant_w_kernel<<<(int)((elems + 255) / 256), 256>>>(idx, scale, lut);
    }
    {
        size_t elems = (size_t)M_DIM * K_DIM / 4;
        convert_x_kernel<<<(int)((elems + 255) / 256), 256>>>(x);
    }
    {
        cudaFuncSetAttribute(gemm_hmma_kernel,
                             cudaFuncAttributeMaxDynamicSharedMemorySize, SMEM_TOTAL);
        dim3 grid(N_DIM / BN, M_DIM / BM);   // 32 x 64
        gemm_hmma_kernel<<<grid, 256, SMEM_TOTAL>>>(out);
    }
}

// round 4
// speedup vs baseline: 1.9960x; 1.1059x over previous
#include <cuda_runtime.h>
#include <cuda_fp16.h>
#include <cstdint>

// Problem dims (fixed by the dataset)
#define M_DIM 8192   // B*S
#define N_DIM 4096   // OUT_F
#define K_DIM 4096   // IN_F

// GEMM tiling: CTA 128x256, warp 64x64, 8 warps (2m x 4n)
#define BM 128
#define BN 256
#define BK 64                      // 64 halves = 128B rows (SW128 atom)
#define NSTAGES 4
#define KSTEPS (K_DIM / BK)        // 64

#define A_STAGE_BYTES (BM * 128)   // 16 KB
#define B_STAGE_BYTES (BN * 128)   // 32 KB
#define STAGE_BYTES   (A_STAGE_BYTES + B_STAGE_BYTES)   // 48 KB
#define SMEM_TOTAL    (NSTAGES * STAGE_BYTES)           // 192 KB

// Scratch (no cudaMalloc allowed)
__device__ __half g_W[(size_t)N_DIM * K_DIM];   // 32 MB dequantized weights
__device__ __half g_X[(size_t)M_DIM * K_DIM];   // 64 MB fp16 activations

// ---------------------------------------------------------------------------
// helpers
// ---------------------------------------------------------------------------
static __device__ __forceinline__ uint32_t s2u(const void* p) {
    uint32_t a;
    asm("{ .reg .u64 t; cvta.to.shared.u64 t, %1; cvt.u32.u64 %0, t; }"
        : "=r"(a) : "l"(p));
    return a;
}

static __device__ __forceinline__ void cp_async16(uint32_t dst, const void* src) {
    asm volatile("cp.async.cg.shared.global [%0], [%1], 16;"
                 :: "r"(dst), "l"(src) : "memory");
}
#define CP_COMMIT() asm volatile("cp.async.commit_group;" ::: "memory")
#define CP_WAIT2()  asm volatile("cp.async.wait_group 2;" ::: "memory")
#define CP_WAIT0()  asm volatile("cp.async.wait_group 0;" ::: "memory")

#define LDSM_X4(r0, r1, r2, r3, a) \
    asm volatile("ldmatrix.sync.aligned.m8n8.x4.shared.b16 {%0,%1,%2,%3}, [%4];" \
                 : "=r"(r0), "=r"(r1), "=r"(r2), "=r"(r3) : "r"(a))

static __device__ __forceinline__ void mma16816(float* c, const uint32_t* a,
                                                const uint32_t* b) {
    asm volatile(
        "mma.sync.aligned.m16n8k16.row.col.f32.f16.f16.f32 "
        "{%0,%1,%2,%3}, {%4,%5,%6,%7}, {%8,%9}, {%0,%1,%2,%3};"
        : "+f"(c[0]), "+f"(c[1]), "+f"(c[2]), "+f"(c[3])
        : "r"(a[0]), "r"(a[1]), "r"(a[2]), "r"(a[3]), "r"(b[0]), "r"(b[1]));
}

// ---------------------------------------------------------------------------
// Kernel 1: dequantize W[o,i] = lut[idx[o,i]] * scale[o]  -> fp16
// 8 codes / thread (2x int4 loads, 1x uint4 store).
// ---------------------------------------------------------------------------
__global__ void dequant_w_kernel(const int* __restrict__ idx,
                                 const float* __restrict__ scale,
                                 const float* __restrict__ lut) {
    size_t t = (size_t)blockIdx.x * blockDim.x + threadIdx.x;
    size_t base = t * 8;
    if (base >= (size_t)N_DIM * K_DIM) return;
    int row = (int)(base / K_DIM);
    float s = scale[row];
    int4 c0 = *reinterpret_cast<const int4*>(idx + base);
    int4 c1 = *reinterpret_cast<const int4*>(idx + base + 4);
    __half2 h[4];
    h[0] = __floats2half2_rn(lut[c0.x] * s, lut[c0.y] * s);
    h[1] = __floats2half2_rn(lut[c0.z] * s, lut[c0.w] * s);
    h[2] = __floats2half2_rn(lut[c1.x] * s, lut[c1.y] * s);
    h[3] = __floats2half2_rn(lut[c1.z] * s, lut[c1.w] * s);
    *reinterpret_cast<uint4*>(g_W + base) = *reinterpret_cast<uint4*>(h);
}

// ---------------------------------------------------------------------------
// Kernel 2: convert x fp32 -> fp16, 8 elems / thread
// ---------------------------------------------------------------------------
__global__ void convert_x_kernel(const float* __restrict__ x) {
    size_t t = (size_t)blockIdx.x * blockDim.x + threadIdx.x;
    size_t base = t * 8;
    if (base >= (size_t)M_DIM * K_DIM) return;
    float4 v0 = *reinterpret_cast<const float4*>(x + base);
    float4 v1 = *reinterpret_cast<const float4*>(x + base + 4);
    __half2 h[4];
    h[0] = __floats2half2_rn(v0.x, v0.y);
    h[1] = __floats2half2_rn(v0.z, v0.w);
    h[2] = __floats2half2_rn(v1.x, v1.y);
    h[3] = __floats2half2_rn(v1.z, v1.w);
    *reinterpret_cast<uint4*>(g_X + base) = *reinterpret_cast<uint4*>(h);
}

// ---------------------------------------------------------------------------
// Kernel 3: HMMA GEMM. CTA 128x256, BK=64, 8 warps (2m x 4n), warp tile 64x64.
// 4-stage cp.async pipeline, SW128-swizzled smem, ldmatrix.x4, mma.sync 16816.
//   out[m,n] = sum_k X[m,k] * W[n,k]
// ---------------------------------------------------------------------------
__device__ __forceinline__ void load_stage(int tid, uint32_t sb, int s, int kstep,
                                           const char* Ag, const char* Bg) {
    uint32_t SA = sb + s * STAGE_BYTES;
    uint32_t SB = SA + A_STAGE_BYTES;
    const size_t krow = (size_t)K_DIM * 2;           // row stride bytes
    const char* Akp = Ag + (size_t)kstep * 128;      // +kstep*64 halves
    const char* Bkp = Bg + (size_t)kstep * 128;
    // A: 128 rows x 8 chunks = 1024, 4 per thread
    #pragma unroll
    for (int j = 0; j < 4; j++) {
        int cid = tid + 256 * j;
        int row = cid >> 3;
        int c   = cid & 7;
        uint32_t sw = (uint32_t)(row * 128 + ((c ^ (row & 7)) * 16));
        cp_async16(SA + sw, Akp + (size_t)row * krow + c * 16);
    }
    // B: 256 rows x 8 chunks = 2048, 8 per thread
    #pragma unroll
    for (int j = 0; j < 8; j++) {
        int cid = tid + 256 * j;
        int row = cid >> 3;
        int c   = cid & 7;
        uint32_t sw = (uint32_t)(row * 128 + ((c ^ (row & 7)) * 16));
        cp_async16(SB + sw, Bkp + (size_t)row * krow + c * 16);
    }
}

__global__ void __launch_bounds__(256, 1)
gemm_hmma_kernel(float* __restrict__ out) {
    extern __shared__ __align__(1024) char smem[];
    const uint32_t sb = s2u(smem);
    const int tid = threadIdx.x;
    const int wid = tid >> 5;
    const int lid = tid & 31;
    const int wm = wid & 1;        // 0..1 : 64-row slab
    const int wn = wid >> 1;       // 0..3 : 64-col slab
    const int m0 = blockIdx.y * BM;
    const int n0 = blockIdx.x * BN;

    const char* Ag = (const char*)(g_X + (size_t)m0 * K_DIM);
    const char* Bg = (const char*)(g_W + (size_t)n0 * K_DIM);

    // per-lane ldmatrix address components (stage-relative)
    uint32_t a_rowoff[4], b_rowoff[4];
    #pragma unroll
    for (int i = 0; i < 4; i++)
        a_rowoff[i] = (uint32_t)((wm * 64 + i * 16 + (lid & 15)) * 128);
    #pragma unroll
    for (int j2 = 0; j2 < 4; j2++)
        b_rowoff[j2] = (uint32_t)((wn * 64 + j2 * 16 + (lid & 7) +
                                   ((lid >> 4) & 1) * 8) * 128);
    uint32_t a_ch[4], b_ch[4];
    #pragma unroll
    for (int q = 0; q < 4; q++) {
        a_ch[q] = (uint32_t)((((2 * q + (lid >> 4)) ^ (lid & 7)) * 16));
        b_ch[q] = (uint32_t)((((2 * q + ((lid >> 3) & 1)) ^ (lid & 7)) * 16));
    }

    float acc[4][8][4];
    #pragma unroll
    for (int i = 0; i < 4; i++)
        #pragma unroll
        for (int j = 0; j < 8; j++)
            #pragma unroll
            for (int r = 0; r < 4; r++)
                acc[i][j][r] = 0.0f;

    // Prologue: fill stages 0..2
    #pragma unroll
    for (int s = 0; s < NSTAGES - 1; s++) {
        load_stage(tid, sb, s, s, Ag, Bg);
        CP_COMMIT();
    }

    uint32_t a_frag[2][4][4];
    uint32_t b_frag[2][4][4];

    for (int i = 0; i < KSTEPS; i++) {
        CP_WAIT2();
        __syncthreads();
        if (i + NSTAGES - 1 < KSTEPS)
            load_stage(tid, sb, (i + NSTAGES - 1) & (NSTAGES - 1),
                       i + NSTAGES - 1, Ag, Bg);
        CP_COMMIT();

        const uint32_t SA = sb + (i & (NSTAGES - 1)) * STAGE_BYTES;
        const uint32_t SB = SA + A_STAGE_BYTES;

        // prefetch q=0 fragments
        #pragma unroll
        for (int t4 = 0; t4 < 4; t4++)
            LDSM_X4(a_frag[0][t4][0], a_frag[0][t4][1],
                    a_frag[0][t4][2], a_frag[0][t4][3],
                    SA + a_rowoff[t4] + a_ch[0]);
        #pragma unroll
        for (int j2 = 0; j2 < 4; j2++)
            LDSM_X4(b_frag[0][j2][0], b_frag[0][j2][1],
                    b_frag[0][j2][2], b_frag[0][j2][3],
                    SB + b_rowoff[j2] + b_ch[0]);

        #pragma unroll
        for (int q = 0; q < 4; q++) {
            const int cur = q & 1, nxt = cur ^ 1;
            if (q < 3) {
                #pragma unroll
                for (int t4 = 0; t4 < 4; t4++)
                    LDSM_X4(a_frag[nxt][t4][0], a_frag[nxt][t4][1],
                            a_frag[nxt][t4][2], a_frag[nxt][t4][3],
                            SA + a_rowoff[t4] + a_ch[q + 1]);
                #pragma unroll
                for (int j2 = 0; j2 < 4; j2++)
                    LDSM_X4(b_frag[nxt][j2][0], b_frag[nxt][j2][1],
                            b_frag[nxt][j2][2], b_frag[nxt][j2][3],
                            SB + b_rowoff[j2] + b_ch[q + 1]);
            }
            #pragma unroll
            for (int t4 = 0; t4 < 4; t4++)
                #pragma unroll
                for (int j = 0; j < 8; j++)
                    mma16816(acc[t4][j], a_frag[cur][t4],
                             &b_frag[cur][j >> 1][(j & 1) * 2]);
        }
    }
    CP_WAIT0();

    // Epilogue: c{0,1} -> (row g, col 2tc), c{2,3} -> (row g+8, col 2tc)
    const int g  = lid >> 2;
    const int tc = lid & 3;
    float* Cb = out + (size_t)(m0 + wm * 64) * N_DIM + n0 + wn * 64;
    #pragma unroll
    for (int t4 = 0; t4 < 4; t4++) {
        #pragma unroll
        for (int j = 0; j < 8; j++) {
            float* p0 = Cb + (size_t)(t4 * 16 + g) * N_DIM + j * 8 + tc * 2;
            float* p1 = p0 + 8 * N_DIM;
            *reinterpret_cast<float2*>(p0) = make_float2(acc[t4][j][0], acc[t4][j][1]);
            *reinterpret_cast<float2*>(p1) = make_float2(acc[t4][j][2], acc[t4][j][3]);
        }
    }
}

// ---------------------------------------------------------------------------
// Entry point. Inputs: x f32, grid_indices i32, scale f32, lut f32.
// Output: float32 [8192, 4096].
// ---------------------------------------------------------------------------
extern "C" void kernel_launch(void* const* d_in, const int* in_sizes, int n_in,
                              void* d_out, int out_size) {
    const float* x     = (const float*)d_in[0];
    const int*   idx   = (const int*)  d_in[1];
    const float* scale = (const float*)d_in[2];
    const float* lut   = (const float*)d_in[3];
    float* out = (float*)d_out;

    {
        size_t elems = (size_t)N_DIM * K_DIM / 8;
        dequant_w_kernel<<<(int)((elems + 255) / 256), 256>>>(idx, scale, lut);
    }
    {
        size_t elems = (size_t)M_DIM * K_DIM / 8;
        convert_x_kernel<<<(int)((elems + 255) / 256), 256>>>(x);
    }
    {
        cudaFuncSetAttribute(gemm_hmma_kernel,
                             cudaFuncAttributeMaxDynamicSharedMemorySize, SMEM_TOTAL);
        dim3 grid(N_DIM / BN, M_DIM / BM);   // 16 x 64
        gemm_hmma_kernel<<<grid, 256, SMEM_TOTAL>>>(out);
    }
}

// round 5
// speedup vs baseline: 2.1930x; 1.0987x over previous
#include <cuda_runtime.h>
#include <cuda_fp16.h>
#include <cstdint>

// Problem dims (fixed by the dataset)
#define M_DIM 8192   // B*S
#define N_DIM 4096   // OUT_F
#define K_DIM 4096   // IN_F

// GEMM tiling: CTA 128x128, 4 warps (2m x 2n), warp tile 64x64
#define BM 128
#define BN 128
#define BK 64                      // 64 halves = 128B rows (SW128 atom)
#define NSTAGES 3
#define KSTEPS (K_DIM / BK)        // 64

#define A_STAGE_BYTES (BM * 128)   // 16 KB
#define B_STAGE_BYTES (BN * 128)   // 16 KB
#define STAGE_BYTES   (A_STAGE_BYTES + B_STAGE_BYTES)   // 32 KB
#define SMEM_TOTAL    (NSTAGES * STAGE_BYTES)           // 96 KB -> 2 CTAs/SM

// Scratch (no cudaMalloc allowed)
__device__ __half g_W[(size_t)N_DIM * K_DIM];   // 32 MB dequantized weights
__device__ __half g_X[(size_t)M_DIM * K_DIM];   // 64 MB fp16 activations

// ---------------------------------------------------------------------------
// helpers
// ---------------------------------------------------------------------------
static __device__ __forceinline__ uint32_t s2u(const void* p) {
    uint32_t a;
    asm("{ .reg .u64 t; cvta.to.shared.u64 t, %1; cvt.u32.u64 %0, t; }"
        : "=r"(a) : "l"(p));
    return a;
}

static __device__ __forceinline__ void cp_async16(uint32_t dst, const void* src) {
    asm volatile("cp.async.cg.shared.global [%0], [%1], 16;"
                 :: "r"(dst), "l"(src) : "memory");
}
#define CP_COMMIT() asm volatile("cp.async.commit_group;" ::: "memory")
#define CP_WAIT1()  asm volatile("cp.async.wait_group 1;" ::: "memory")
#define CP_WAIT0()  asm volatile("cp.async.wait_group 0;" ::: "memory")

#define LDSM_X4(r0, r1, r2, r3, a) \
    asm volatile("ldmatrix.sync.aligned.m8n8.x4.shared.b16 {%0,%1,%2,%3}, [%4];" \
                 : "=r"(r0), "=r"(r1), "=r"(r2), "=r"(r3) : "r"(a))

static __device__ __forceinline__ void mma16816(float* c, const uint32_t* a,
                                                const uint32_t* b) {
    asm volatile(
        "mma.sync.aligned.m16n8k16.row.col.f32.f16.f16.f32 "
        "{%0,%1,%2,%3}, {%4,%5,%6,%7}, {%8,%9}, {%0,%1,%2,%3};"
        : "+f"(c[0]), "+f"(c[1]), "+f"(c[2]), "+f"(c[3])
        : "r"(a[0]), "r"(a[1]), "r"(a[2]), "r"(a[3]), "r"(b[0]), "r"(b[1]));
}

// ---------------------------------------------------------------------------
// Kernel 1: dequantize W[o,i] = lut[idx[o,i]] * scale[o]  -> fp16
// 16 codes / thread (4x int4 loads in flight, 2x uint4 stores).
// ---------------------------------------------------------------------------
__global__ void dequant_w_kernel(const int* __restrict__ idx,
                                 const float* __restrict__ scale,
                                 const float* __restrict__ lut) {
    size_t t = (size_t)blockIdx.x * blockDim.x + threadIdx.x;
    size_t base = t * 16;
    if (base >= (size_t)N_DIM * K_DIM) return;
    int row = (int)(base / K_DIM);
    float s = scale[row];
    int4 c[4];
    #pragma unroll
    for (int i = 0; i < 4; i++)
        c[i] = *reinterpret_cast<const int4*>(idx + base + i * 4);
    __half2 h[8];
    #pragma unroll
    for (int i = 0; i < 4; i++) {
        h[i * 2 + 0] = __floats2half2_rn(lut[c[i].x] * s, lut[c[i].y] * s);
        h[i * 2 + 1] = __floats2half2_rn(lut[c[i].z] * s, lut[c[i].w] * s);
    }
    *reinterpret_cast<uint4*>(g_W + base)     = *reinterpret_cast<uint4*>(h);
    *reinterpret_cast<uint4*>(g_W + base + 8) = *reinterpret_cast<uint4*>(h + 4);
}

// ---------------------------------------------------------------------------
// Kernel 2: convert x fp32 -> fp16, 16 elems / thread
// ---------------------------------------------------------------------------
__global__ void convert_x_kernel(const float* __restrict__ x) {
    size_t t = (size_t)blockIdx.x * blockDim.x + threadIdx.x;
    size_t base = t * 16;
    if (base >= (size_t)M_DIM * K_DIM) return;
    float4 v[4];
    #pragma unroll
    for (int i = 0; i < 4; i++)
        v[i] = *reinterpret_cast<const float4*>(x + base + i * 4);
    __half2 h[8];
    #pragma unroll
    for (int i = 0; i < 4; i++) {
        h[i * 2 + 0] = __floats2half2_rn(v[i].x, v[i].y);
        h[i * 2 + 1] = __floats2half2_rn(v[i].z, v[i].w);
    }
    *reinterpret_cast<uint4*>(g_X + base)     = *reinterpret_cast<uint4*>(h);
    *reinterpret_cast<uint4*>(g_X + base + 8) = *reinterpret_cast<uint4*>(h + 4);
}

// ---------------------------------------------------------------------------
// Kernel 3: HMMA GEMM. CTA 128x128, BK=64, 4 warps (2m x 2n), warp tile 64x64.
// 3-stage cp.async pipeline, SW128-swizzled smem, ldmatrix.x4, mma.sync 16816.
// 2 CTAs/SM for cross-CTA latency hiding.
//   out[m,n] = sum_k X[m,k] * W[n,k]
// ---------------------------------------------------------------------------
__device__ __forceinline__ void load_stage(int tid, uint32_t sb, int s, int kstep,
                                           const char* Ag, const char* Bg) {
    uint32_t SA = sb + s * STAGE_BYTES;
    uint32_t SB = SA + A_STAGE_BYTES;
    const size_t krow = (size_t)K_DIM * 2;           // row stride bytes
    const char* Akp = Ag + (size_t)kstep * 128;      // +kstep*64 halves
    const char* Bkp = Bg + (size_t)kstep * 128;
    // A and B: 128 rows x 8 chunks = 1024 chunks each, 8 per thread
    #pragma unroll
    for (int j = 0; j < 8; j++) {
        int cid = tid + 128 * j;
        int row = cid >> 3;
        int c   = cid & 7;
        uint32_t sw = (uint32_t)(row * 128 + ((c ^ (row & 7)) * 16));
        cp_async16(SA + sw, Akp + (size_t)row * krow + c * 16);
        cp_async16(SB + sw, Bkp + (size_t)row * krow + c * 16);
    }
}

__global__ void __launch_bounds__(128, 2)
gemm_hmma_kernel(float* __restrict__ out) {
    extern __shared__ __align__(1024) char smem[];
    const uint32_t sb = s2u(smem);
    const int tid = threadIdx.x;
    const int wid = tid >> 5;
    const int lid = tid & 31;
    const int wm = wid & 1;        // 0..1 : 64-row slab
    const int wn = wid >> 1;       // 0..1 : 64-col slab
    const int m0 = blockIdx.y * BM;
    const int n0 = blockIdx.x * BN;

    const char* Ag = (const char*)(g_X + (size_t)m0 * K_DIM);
    const char* Bg = (const char*)(g_W + (size_t)n0 * K_DIM);

    // per-lane ldmatrix address components (stage-relative)
    uint32_t a_rowoff[4], b_rowoff[4];
    #pragma unroll
    for (int i = 0; i < 4; i++)
        a_rowoff[i] = (uint32_t)((wm * 64 + i * 16 + (lid & 15)) * 128);
    #pragma unroll
    for (int j2 = 0; j2 < 4; j2++)
        b_rowoff[j2] = (uint32_t)((wn * 64 + j2 * 16 + (lid & 7) +
                                   ((lid >> 4) & 1) * 8) * 128);
    uint32_t a_ch[4], b_ch[4];
    #pragma unroll
    for (int q = 0; q < 4; q++) {
        a_ch[q] = (uint32_t)((((2 * q + (lid >> 4)) ^ (lid & 7)) * 16));
        b_ch[q] = (uint32_t)((((2 * q + ((lid >> 3) & 1)) ^ (lid & 7)) * 16));
    }

    float acc[4][8][4];
    #pragma unroll
    for (int i = 0; i < 4; i++)
        #pragma unroll
        for (int j = 0; j < 8; j++)
            #pragma unroll
            for (int r = 0; r < 4; r++)
                acc[i][j][r] = 0.0f;

    // Prologue: fill stages 0..1
    #pragma unroll
    for (int s = 0; s < NSTAGES - 1; s++) {
        load_stage(tid, sb, s, s, Ag, Bg);
        CP_COMMIT();
    }

    uint32_t a_frag[2][4][4];
    uint32_t b_frag[2][4][4];

    for (int i = 0; i < KSTEPS; i++) {
        CP_WAIT1();
        __syncthreads();
        if (i + NSTAGES - 1 < KSTEPS) {
            int s = (i + NSTAGES - 1) % NSTAGES;
            load_stage(tid, sb, s, i + NSTAGES - 1, Ag, Bg);
        }
        CP_COMMIT();

        const uint32_t SA = sb + (i % NSTAGES) * STAGE_BYTES;
        const uint32_t SB = SA + A_STAGE_BYTES;

        // prefetch q=0 fragments
        #pragma unroll
        for (int t4 = 0; t4 < 4; t4++)
            LDSM_X4(a_frag[0][t4][0], a_frag[0][t4][1],
                    a_frag[0][t4][2], a_frag[0][t4][3],
                    SA + a_rowoff[t4] + a_ch[0]);
        #pragma unroll
        for (int j2 = 0; j2 < 4; j2++)
            LDSM_X4(b_frag[0][j2][0], b_frag[0][j2][1],
                    b_frag[0][j2][2], b_frag[0][j2][3],
                    SB + b_rowoff[j2] + b_ch[0]);

        #pragma unroll
        for (int q = 0; q < 4; q++) {
            const int cur = q & 1, nxt = cur ^ 1;
            if (q < 3) {
                #pragma unroll
                for (int t4 = 0; t4 < 4; t4++)
                    LDSM_X4(a_frag[nxt][t4][0], a_frag[nxt][t4][1],
                            a_frag[nxt][t4][2], a_frag[nxt][t4][3],
                            SA + a_rowoff[t4] + a_ch[q + 1]);
                #pragma unroll
                for (int j2 = 0; j2 < 4; j2++)
                    LDSM_X4(b_frag[nxt][j2][0], b_frag[nxt][j2][1],
                            b_frag[nxt][j2][2], b_frag[nxt][j2][3],
                            SB + b_rowoff[j2] + b_ch[q + 1]);
            }
            #pragma unroll
            for (int t4 = 0; t4 < 4; t4++)
                #pragma unroll
                for (int j = 0; j < 8; j++)
                    mma16816(acc[t4][j], a_frag[cur][t4],
                             &b_frag[cur][j >> 1][(j & 1) * 2]);
        }
    }
    CP_WAIT0();

    // Epilogue: c{0,1} -> (row g, col 2tc), c{2,3} -> (row g+8, col 2tc)
    const int g  = lid >> 2;
    const int tc = lid & 3;
    float* Cb = out + (size_t)(m0 + wm * 64) * N_DIM + n0 + wn * 64;
    #pragma unroll
    for (int t4 = 0; t4 < 4; t4++) {
        #pragma unroll
        for (int j = 0; j < 8; j++) {
            float* p0 = Cb + (size_t)(t4 * 16 + g) * N_DIM + j * 8 + tc * 2;
            float* p1 = p0 + 8 * N_DIM;
            *reinterpret_cast<float2*>(p0) = make_float2(acc[t4][j][0], acc[t4][j][1]);
            *reinterpret_cast<float2*>(p1) = make_float2(acc[t4][j][2], acc[t4][j][3]);
        }
    }
}

// ---------------------------------------------------------------------------
// Entry point. Inputs: x f32, grid_indices i32, scale f32, lut f32.
// Output: float32 [8192, 4096].
// ---------------------------------------------------------------------------
extern "C" void kernel_launch(void* const* d_in, const int* in_sizes, int n_in,
                              void* d_out, int out_size) {
    const float* x     = (const float*)d_in[0];
    const int*   idx   = (const int*)  d_in[1];
    const float* scale = (const float*)d_in[2];
    const float* lut   = (const float*)d_in[3];
    float* out = (float*)d_out;

    {
        size_t elems = (size_t)N_DIM * K_DIM / 16;
        dequant_w_kernel<<<(int)((elems + 255) / 256), 256>>>(idx, scale, lut);
    }
    {
        size_t elems = (size_t)M_DIM * K_DIM / 16;
        convert_x_kernel<<<(int)((elems + 255) / 256), 256>>>(x);
    }
    {
        cudaFuncSetAttribute(gemm_hmma_kernel,
                             cudaFuncAttributeMaxDynamicSharedMemorySize, SMEM_TOTAL);
        dim3 grid(N_DIM / BN, M_DIM / BM);   // 32 x 64
        gemm_hmma_kernel<<<grid, 128, SMEM_TOTAL>>>(out);
    }
}

// round 6
// speedup vs baseline: 2.3911x; 1.0903x over previous
#include <cuda_runtime.h>
#include <cuda_fp16.h>
#include <cstdint>

// Problem dims (fixed by the dataset)
#define M_DIM 8192   // B*S
#define N_DIM 4096   // OUT_F
#define K_DIM 4096   // IN_F

// GEMM tiling: CTA 128x128, 4 warps (2m x 2n), warp tile 64x64
#define BM 128
#define BN 128
#define BK 64                      // 64 halves = 128B rows (SW128 atom)
#define NSTAGES 3
#define KSTEPS (K_DIM / BK)        // 64

#define A_STAGE_BYTES (BM * 128)   // 16 KB
#define B_STAGE_BYTES (BN * 128)   // 16 KB
#define STAGE_BYTES   (A_STAGE_BYTES + B_STAGE_BYTES)   // 32 KB
#define SMEM_TOTAL    (NSTAGES * STAGE_BYTES)           // 96 KB -> 2 CTAs/SM

// Scratch (no cudaMalloc allowed)
__device__ __half g_W[(size_t)N_DIM * K_DIM];   // 32 MB dequantized weights
__device__ __half g_X[(size_t)M_DIM * K_DIM];   // 64 MB fp16 activations

// ---------------------------------------------------------------------------
// helpers
// ---------------------------------------------------------------------------
static __device__ __forceinline__ uint32_t s2u(const void* p) {
    uint32_t a;
    asm("{ .reg .u64 t; cvta.to.shared.u64 t, %1; cvt.u32.u64 %0, t; }"
        : "=r"(a) : "l"(p));
    return a;
}

static __device__ __forceinline__ void cp_async16(uint32_t dst, const void* src) {
    asm volatile("cp.async.cg.shared.global [%0], [%1], 16;"
                 :: "r"(dst), "l"(src) : "memory");
}
#define CP_COMMIT() asm volatile("cp.async.commit_group;" ::: "memory")
#define CP_WAIT1()  asm volatile("cp.async.wait_group 1;" ::: "memory")
#define CP_WAIT0()  asm volatile("cp.async.wait_group 0;" ::: "memory")

#define LDSM_X4(r0, r1, r2, r3, a) \
    asm volatile("ldmatrix.sync.aligned.m8n8.x4.shared.b16 {%0,%1,%2,%3}, [%4];" \
                 : "=r"(r0), "=r"(r1), "=r"(r2), "=r"(r3) : "r"(a))

static __device__ __forceinline__ void mma16816(float* c, const uint32_t* a,
                                                const uint32_t* b) {
    asm volatile(
        "mma.sync.aligned.m16n8k16.row.col.f32.f16.f16.f32 "
        "{%0,%1,%2,%3}, {%4,%5,%6,%7}, {%8,%9}, {%0,%1,%2,%3};"
        : "+f"(c[0]), "+f"(c[1]), "+f"(c[2]), "+f"(c[3])
        : "r"(a[0]), "r"(a[1]), "r"(a[2]), "r"(a[3]), "r"(b[0]), "r"(b[1]));
}

// ---------------------------------------------------------------------------
// Kernel 1: dequantize W[o,i] = lut[idx[o,i]] * scale[o]  -> fp16
// 8 codes / thread (measured-best vectorization).
// ---------------------------------------------------------------------------
__global__ void dequant_w_kernel(const int* __restrict__ idx,
                                 const float* __restrict__ scale,
                                 const float* __restrict__ lut) {
    size_t t = (size_t)blockIdx.x * blockDim.x + threadIdx.x;
    size_t base = t * 8;
    if (base >= (size_t)N_DIM * K_DIM) return;
    int row = (int)(base / K_DIM);
    float s = scale[row];
    int4 c0 = *reinterpret_cast<const int4*>(idx + base);
    int4 c1 = *reinterpret_cast<const int4*>(idx + base + 4);
    __half2 h[4];
    h[0] = __floats2half2_rn(lut[c0.x] * s, lut[c0.y] * s);
    h[1] = __floats2half2_rn(lut[c0.z] * s, lut[c0.w] * s);
    h[2] = __floats2half2_rn(lut[c1.x] * s, lut[c1.y] * s);
    h[3] = __floats2half2_rn(lut[c1.z] * s, lut[c1.w] * s);
    *reinterpret_cast<uint4*>(g_W + base) = *reinterpret_cast<uint4*>(h);
}

// ---------------------------------------------------------------------------
// Kernel 2: convert x fp32 -> fp16, 8 elems / thread
// ---------------------------------------------------------------------------
__global__ void convert_x_kernel(const float* __restrict__ x) {
    size_t t = (size_t)blockIdx.x * blockDim.x + threadIdx.x;
    size_t base = t * 8;
    if (base >= (size_t)M_DIM * K_DIM) return;
    float4 v0 = *reinterpret_cast<const float4*>(x + base);
    float4 v1 = *reinterpret_cast<const float4*>(x + base + 4);
    __half2 h[4];
    h[0] = __floats2half2_rn(v0.x, v0.y);
    h[1] = __floats2half2_rn(v0.z, v0.w);
    h[2] = __floats2half2_rn(v1.x, v1.y);
    h[3] = __floats2half2_rn(v1.z, v1.w);
    *reinterpret_cast<uint4*>(g_X + base) = *reinterpret_cast<uint4*>(h);
}

// ---------------------------------------------------------------------------
// Kernel 3: HMMA GEMM. CTA 128x128, BK=64, 4 warps (2m x 2n), warp tile 64x64.
// 3-stage cp.async pipeline, SW128-swizzled smem, ldmatrix.x4, mma.sync 16816.
// 2 CTAs/SM. Stage refill issued AFTER the q0 fragment prefetch so the HMMA
// dependency chain starts immediately each kstep.
//   out[m,n] = sum_k X[m,k] * W[n,k]
// ---------------------------------------------------------------------------
__device__ __forceinline__ void load_stage(int tid, uint32_t sb, int s, int kstep,
                                           const char* Ag, const char* Bg) {
    uint32_t SA = sb + s * STAGE_BYTES;
    uint32_t SB = SA + A_STAGE_BYTES;
    const size_t krow = (size_t)K_DIM * 2;           // row stride bytes
    const char* Akp = Ag + (size_t)kstep * 128;      // +kstep*64 halves
    const char* Bkp = Bg + (size_t)kstep * 128;
    #pragma unroll
    for (int j = 0; j < 8; j++) {
        int cid = tid + 128 * j;
        int row = cid >> 3;
        int c   = cid & 7;
        uint32_t sw = (uint32_t)(row * 128 + ((c ^ (row & 7)) * 16));
        cp_async16(SA + sw, Akp + (size_t)row * krow + c * 16);
        cp_async16(SB + sw, Bkp + (size_t)row * krow + c * 16);
    }
}

__global__ void __launch_bounds__(128, 2)
gemm_hmma_kernel(float* __restrict__ out) {
    extern __shared__ __align__(1024) char smem[];
    const uint32_t sb = s2u(smem);
    const int tid = threadIdx.x;
    const int wid = tid >> 5;
    const int lid = tid & 31;
    const int wm = wid & 1;        // 0..1 : 64-row slab
    const int wn = wid >> 1;       // 0..1 : 64-col slab
    const int m0 = blockIdx.y * BM;
    const int n0 = blockIdx.x * BN;

    const char* Ag = (const char*)(g_X + (size_t)m0 * K_DIM);
    const char* Bg = (const char*)(g_W + (size_t)n0 * K_DIM);

    // per-lane ldmatrix address components (stage-relative)
    uint32_t a_rowoff[4], b_rowoff[4];
    #pragma unroll
    for (int i = 0; i < 4; i++)
        a_rowoff[i] = (uint32_t)((wm * 64 + i * 16 + (lid & 15)) * 128);
    #pragma unroll
    for (int j2 = 0; j2 < 4; j2++)
        b_rowoff[j2] = (uint32_t)((wn * 64 + j2 * 16 + (lid & 7) +
                                   ((lid >> 4) & 1) * 8) * 128);
    uint32_t a_ch[4], b_ch[4];
    #pragma unroll
    for (int q = 0; q < 4; q++) {
        a_ch[q] = (uint32_t)((((2 * q + (lid >> 4)) ^ (lid & 7)) * 16));
        b_ch[q] = (uint32_t)((((2 * q + ((lid >> 3) & 1)) ^ (lid & 7)) * 16));
    }

    float acc[4][8][4];
    #pragma unroll
    for (int i = 0; i < 4; i++)
        #pragma unroll
        for (int j = 0; j < 8; j++)
            #pragma unroll
            for (int r = 0; r < 4; r++)
                acc[i][j][r] = 0.0f;

    // Prologue: fill stages 0..1
    load_stage(tid, sb, 0, 0, Ag, Bg);
    CP_COMMIT();
    load_stage(tid, sb, 1, 1, Ag, Bg);
    CP_COMMIT();

    uint32_t a_frag[2][4][4];
    uint32_t b_frag[2][4][4];

    int s_cur = 0;                 // stage being consumed
    int s_nxt = 2;                 // stage being filled

    #pragma unroll 1
    for (int i = 0; i < KSTEPS; i++) {
        if (i < KSTEPS - 1) CP_WAIT1(); else CP_WAIT0();
        __syncthreads();

        const uint32_t SA = sb + s_cur * STAGE_BYTES;
        const uint32_t SB = SA + A_STAGE_BYTES;

        // q0 fragment prefetch FIRST: start the MMA dependency chain
        #pragma unroll
        for (int t4 = 0; t4 < 4; t4++)
            LDSM_X4(a_frag[0][t4][0], a_frag[0][t4][1],
                    a_frag[0][t4][2], a_frag[0][t4][3],
                    SA + a_rowoff[t4] + a_ch[0]);
        #pragma unroll
        for (int j2 = 0; j2 < 4; j2++)
            LDSM_X4(b_frag[0][j2][0], b_frag[0][j2][1],
                    b_frag[0][j2][2], b_frag[0][j2][3],
                    SB + b_rowoff[j2] + b_ch[0]);

        // then issue next stage's refill (overlaps with MMA stream below)
        if (i + NSTAGES - 1 < KSTEPS) {
            load_stage(tid, sb, s_nxt, i + NSTAGES - 1, Ag, Bg);
            CP_COMMIT();
        }

        #pragma unroll
        for (int q = 0; q < 4; q++) {
            const int cur = q & 1, nxt = cur ^ 1;
            if (q < 3) {
                #pragma unroll
                for (int t4 = 0; t4 < 4; t4++)
                    LDSM_X4(a_frag[nxt][t4][0], a_frag[nxt][t4][1],
                            a_frag[nxt][t4][2], a_frag[nxt][t4][3],
                            SA + a_rowoff[t4] + a_ch[q + 1]);
                #pragma unroll
                for (int j2 = 0; j2 < 4; j2++)
                    LDSM_X4(b_frag[nxt][j2][0], b_frag[nxt][j2][1],
                            b_frag[nxt][j2][2], b_frag[nxt][j2][3],
                            SB + b_rowoff[j2] + b_ch[q + 1]);
            }
            #pragma unroll
            for (int t4 = 0; t4 < 4; t4++)
                #pragma unroll
                for (int j = 0; j < 8; j++)
                    mma16816(acc[t4][j], a_frag[cur][t4],
                             &b_frag[cur][j >> 1][(j & 1) * 2]);
        }

        // ring advance without modulo
        s_cur = (s_cur == NSTAGES - 1) ? 0 : s_cur + 1;
        s_nxt = (s_nxt == NSTAGES - 1) ? 0 : s_nxt + 1;
    }

    // Epilogue: c{0,1} -> (row g, col 2tc), c{2,3} -> (row g+8, col 2tc)
    const int g  = lid >> 2;
    const int tc = lid & 3;
    float* Cb = out + (size_t)(m0 + wm * 64) * N_DIM + n0 + wn * 64;
    #pragma unroll
    for (int t4 = 0; t4 < 4; t4++) {
        #pragma unroll
        for (int j = 0; j < 8; j++) {
            float* p0 = Cb + (size_t)(t4 * 16 + g) * N_DIM + j * 8 + tc * 2;
            float* p1 = p0 + 8 * N_DIM;
            *reinterpret_cast<float2*>(p0) = make_float2(acc[t4][j][0], acc[t4][j][1]);
            *reinterpret_cast<float2*>(p1) = make_float2(acc[t4][j][2], acc[t4][j][3]);
        }
    }
}

// ---------------------------------------------------------------------------
// Entry point. Inputs: x f32, grid_indices i32, scale f32, lut f32.
// Output: float32 [8192, 4096].
// ---------------------------------------------------------------------------
extern "C" void kernel_launch(void* const* d_in, const int* in_sizes, int n_in,
                              void* d_out, int out_size) {
    const float* x     = (const float*)d_in[0];
    const int*   idx   = (const int*)  d_in[1];
    const float* scale = (const float*)d_in[2];
    const float* lut   = (const float*)d_in[3];
    float* out = (float*)d_out;

    {
        size_t elems = (size_t)N_DIM * K_DIM / 8;
        dequant_w_kernel<<<(int)((elems + 255) / 256), 256>>>(idx, scale, lut);
    }
    {
        size_t elems = (size_t)M_DIM * K_DIM / 8;
        convert_x_kernel<<<(int)((elems + 255) / 256), 256>>>(x);
    }
    {
        cudaFuncSetAttribute(gemm_hmma_kernel,
                             cudaFuncAttributeMaxDynamicSharedMemorySize, SMEM_TOTAL);
        dim3 grid(N_DIM / BN, M_DIM / BM);   // 32 x 64
        gemm_hmma_kernel<<<grid, 128, SMEM_TOTAL>>>(out);
    }
}

// round 7
// speedup vs baseline: 2.4016x; 1.0044x over previous
#include <cuda_runtime.h>
#include <cuda_fp16.h>
#include <cstdint>

// Problem dims (fixed by the dataset)
#define M_DIM 8192   // B*S
#define N_DIM 4096   // OUT_F
#define K_DIM 4096   // IN_F

// GEMM tiling: CTA 128x128, 4 warps (2m x 2n), warp tile 64x64
#define BM 128
#define BN 128
#define BK 64                      // 64 halves = 128B rows (SW128 atom)
#define NSTAGES 3
#define KSTEPS (K_DIM / BK)        // 64

#define A_STAGE_BYTES (BM * 128)   // 16 KB
#define B_STAGE_BYTES (BN * 128)   // 16 KB
#define STAGE_BYTES   (A_STAGE_BYTES + B_STAGE_BYTES)   // 32 KB
#define SMEM_TOTAL    (NSTAGES * STAGE_BYTES)           // 96 KB -> 2 CTAs/SM

// Scratch (no cudaMalloc allowed)
__device__ __half g_W[(size_t)N_DIM * K_DIM];   // 32 MB dequantized weights
__device__ __half g_X[(size_t)M_DIM * K_DIM];   // 64 MB fp16 activations

// ---------------------------------------------------------------------------
// helpers
// ---------------------------------------------------------------------------
static __device__ __forceinline__ uint32_t s2u(const void* p) {
    uint32_t a;
    asm("{ .reg .u64 t; cvta.to.shared.u64 t, %1; cvt.u32.u64 %0, t; }"
        : "=r"(a) : "l"(p));
    return a;
}

static __device__ __forceinline__ void cp_async16(uint32_t dst, const void* src) {
    asm volatile("cp.async.cg.shared.global [%0], [%1], 16;"
                 :: "r"(dst), "l"(src) : "memory");
}
#define CP_COMMIT() asm volatile("cp.async.commit_group;" ::: "memory")
#define CP_WAIT1()  asm volatile("cp.async.wait_group 1;" ::: "memory")
#define CP_WAIT0()  asm volatile("cp.async.wait_group 0;" ::: "memory")

#define LDSM_X4(r0, r1, r2, r3, a) \
    asm volatile("ldmatrix.sync.aligned.m8n8.x4.shared.b16 {%0,%1,%2,%3}, [%4];" \
                 : "=r"(r0), "=r"(r1), "=r"(r2), "=r"(r3) : "r"(a))

static __device__ __forceinline__ void mma16816(float* c, const uint32_t* a,
                                                const uint32_t* b) {
    asm volatile(
        "mma.sync.aligned.m16n8k16.row.col.f32.f16.f16.f32 "
        "{%0,%1,%2,%3}, {%4,%5,%6,%7}, {%8,%9}, {%0,%1,%2,%3};"
        : "+f"(c[0]), "+f"(c[1]), "+f"(c[2]), "+f"(c[3])
        : "r"(a[0]), "r"(a[1]), "r"(a[2]), "r"(a[3]), "r"(b[0]), "r"(b[1]));
}

// ---------------------------------------------------------------------------
// Fused prep kernel: interleaved dequant (1/3 of blocks) + convert (2/3).
// Both phases are ~50%-HBM latency-bound alone; co-residency sums their MLP.
//   dequant: W[o,i] = half(lut[idx[o,i]] * scale[o]),  8 codes/thread
//   convert: X = half(x),                              8 elems/thread
// ---------------------------------------------------------------------------
#define DEQ_BLOCKS  ((N_DIM * K_DIM) / (256 * 8))            // 8192
#define CVT_BLOCKS  (((size_t)M_DIM * K_DIM) / (256 * 8))    // 16384
#define PREP_BLOCKS (DEQ_BLOCKS + CVT_BLOCKS)                // 24576

__global__ void prep_kernel(const float* __restrict__ x,
                            const int* __restrict__ idx,
                            const float* __restrict__ scale,
                            const float* __restrict__ lut) {
    int b = blockIdx.x;
    int r3 = b % 3;
    if (r3 == 2) {
        // dequant block: db in [0, 8192)
        int db = b / 3;
        size_t base = ((size_t)db * 256 + threadIdx.x) * 8;
        int row = (int)(base / K_DIM);
        float s = scale[row];
        int4 c0 = *reinterpret_cast<const int4*>(idx + base);
        int4 c1 = *reinterpret_cast<const int4*>(idx + base + 4);
        __half2 h[4];
        h[0] = __floats2half2_rn(lut[c0.x] * s, lut[c0.y] * s);
        h[1] = __floats2half2_rn(lut[c0.z] * s, lut[c0.w] * s);
        h[2] = __floats2half2_rn(lut[c1.x] * s, lut[c1.y] * s);
        h[3] = __floats2half2_rn(lut[c1.z] * s, lut[c1.w] * s);
        *reinterpret_cast<uint4*>(g_W + base) = *reinterpret_cast<uint4*>(h);
    } else {
        // convert block: cb in [0, 16384)
        int cb = (b / 3) * 2 + r3;
        size_t base = ((size_t)cb * 256 + threadIdx.x) * 8;
        float4 v0 = *reinterpret_cast<const float4*>(x + base);
        float4 v1 = *reinterpret_cast<const float4*>(x + base + 4);
        __half2 h[4];
        h[0] = __floats2half2_rn(v0.x, v0.y);
        h[1] = __floats2half2_rn(v0.z, v0.w);
        h[2] = __floats2half2_rn(v1.x, v1.y);
        h[3] = __floats2half2_rn(v1.z, v1.w);
        *reinterpret_cast<uint4*>(g_X + base) = *reinterpret_cast<uint4*>(h);
    }
}

// ---------------------------------------------------------------------------
// HMMA GEMM. CTA 128x128, BK=64, 4 warps (2m x 2n), warp tile 64x64.
// 3-stage cp.async pipeline, SW128-swizzled smem, ldmatrix.x4, mma.sync 16816.
// 2 CTAs/SM. Refill split in two halves (A after q0 prefetch, B after q1
// LDSM issue) to smooth LSU pressure across the kstep.
//   out[m,n] = sum_k X[m,k] * W[n,k]
// ---------------------------------------------------------------------------
__device__ __forceinline__ void load_half(int tid, uint32_t S, int kstep,
                                          const char* Gbase) {
    const size_t krow = (size_t)K_DIM * 2;           // row stride bytes
    const char* Gk = Gbase + (size_t)kstep * 128;    // +kstep*64 halves
    #pragma unroll
    for (int j = 0; j < 8; j++) {
        int cid = tid + 128 * j;
        int row = cid >> 3;
        int c   = cid & 7;
        uint32_t sw = (uint32_t)(row * 128 + ((c ^ (row & 7)) * 16));
        cp_async16(S + sw, Gk + (size_t)row * krow + c * 16);
    }
}

__global__ void __launch_bounds__(128, 2)
gemm_hmma_kernel(float* __restrict__ out) {
    extern __shared__ __align__(1024) char smem[];
    const uint32_t sb = s2u(smem);
    const int tid = threadIdx.x;
    const int wid = tid >> 5;
    const int lid = tid & 31;
    const int wm = wid & 1;        // 0..1 : 64-row slab
    const int wn = wid >> 1;       // 0..1 : 64-col slab
    const int m0 = blockIdx.y * BM;
    const int n0 = blockIdx.x * BN;

    const char* Ag = (const char*)(g_X + (size_t)m0 * K_DIM);
    const char* Bg = (const char*)(g_W + (size_t)n0 * K_DIM);

    // per-lane ldmatrix address components (stage-relative)
    uint32_t a_rowoff[4], b_rowoff[4];
    #pragma unroll
    for (int i = 0; i < 4; i++)
        a_rowoff[i] = (uint32_t)((wm * 64 + i * 16 + (lid & 15)) * 128);
    #pragma unroll
    for (int j2 = 0; j2 < 4; j2++)
        b_rowoff[j2] = (uint32_t)((wn * 64 + j2 * 16 + (lid & 7) +
                                   ((lid >> 4) & 1) * 8) * 128);
    uint32_t a_ch[4], b_ch[4];
    #pragma unroll
    for (int q = 0; q < 4; q++) {
        a_ch[q] = (uint32_t)((((2 * q + (lid >> 4)) ^ (lid & 7)) * 16));
        b_ch[q] = (uint32_t)((((2 * q + ((lid >> 3) & 1)) ^ (lid & 7)) * 16));
    }

    float acc[4][8][4];
    #pragma unroll
    for (int i = 0; i < 4; i++)
        #pragma unroll
        for (int j = 0; j < 8; j++)
            #pragma unroll
            for (int r = 0; r < 4; r++)
                acc[i][j][r] = 0.0f;

    // Prologue: fill stages 0..1
    load_half(tid, sb + 0 * STAGE_BYTES, 0, Ag);
    load_half(tid, sb + 0 * STAGE_BYTES + A_STAGE_BYTES, 0, Bg);
    CP_COMMIT();
    load_half(tid, sb + 1 * STAGE_BYTES, 1, Ag);
    load_half(tid, sb + 1 * STAGE_BYTES + A_STAGE_BYTES, 1, Bg);
    CP_COMMIT();

    uint32_t a_frag[2][4][4];
    uint32_t b_frag[2][4][4];

    int s_cur = 0;                 // stage being consumed
    int s_nxt = 2;                 // stage being filled

    #pragma unroll 1
    for (int i = 0; i < KSTEPS; i++) {
        if (i < KSTEPS - 1) CP_WAIT1(); else CP_WAIT0();
        __syncthreads();

        const uint32_t SA = sb + s_cur * STAGE_BYTES;
        const uint32_t SB = SA + A_STAGE_BYTES;
        const bool refill = (i + NSTAGES - 1 < KSTEPS);
        const uint32_t SNX = sb + s_nxt * STAGE_BYTES;

        // q0 fragment prefetch FIRST: start the MMA dependency chain
        #pragma unroll
        for (int t4 = 0; t4 < 4; t4++)
            LDSM_X4(a_frag[0][t4][0], a_frag[0][t4][1],
                    a_frag[0][t4][2], a_frag[0][t4][3],
                    SA + a_rowoff[t4] + a_ch[0]);
        #pragma unroll
        for (int j2 = 0; j2 < 4; j2++)
            LDSM_X4(b_frag[0][j2][0], b_frag[0][j2][1],
                    b_frag[0][j2][2], b_frag[0][j2][3],
                    SB + b_rowoff[j2] + b_ch[0]);

        // refill A-half: overlaps with first MMA block
        if (refill) load_half(tid, SNX, i + NSTAGES - 1, Ag);

        #pragma unroll
        for (int q = 0; q < 4; q++) {
            const int cur = q & 1, nxt = cur ^ 1;
            if (q < 3) {
                #pragma unroll
                for (int t4 = 0; t4 < 4; t4++)
                    LDSM_X4(a_frag[nxt][t4][0], a_frag[nxt][t4][1],
                            a_frag[nxt][t4][2], a_frag[nxt][t4][3],
                            SA + a_rowoff[t4] + a_ch[q + 1]);
                #pragma unroll
                for (int j2 = 0; j2 < 4; j2++)
                    LDSM_X4(b_frag[nxt][j2][0], b_frag[nxt][j2][1],
                            b_frag[nxt][j2][2], b_frag[nxt][j2][3],
                            SB + b_rowoff[j2] + b_ch[q + 1]);
            }
            if (q == 0 && refill) {
                // refill B-half + single commit for the whole stage
                load_half(tid, SNX + A_STAGE_BYTES, i + NSTAGES - 1, Bg);
                CP_COMMIT();
            }
            #pragma unroll
            for (int t4 = 0; t4 < 4; t4++)
                #pragma unroll
                for (int j = 0; j < 8; j++)
                    mma16816(acc[t4][j], a_frag[cur][t4],
                             &b_frag[cur][j >> 1][(j & 1) * 2]);
        }

        // ring advance without modulo
        s_cur = (s_cur == NSTAGES - 1) ? 0 : s_cur + 1;
        s_nxt = (s_nxt == NSTAGES - 1) ? 0 : s_nxt + 1;
    }

    // Epilogue: c{0,1} -> (row g, col 2tc), c{2,3} -> (row g+8, col 2tc)
    const int g  = lid >> 2;
    const int tc = lid & 3;
    float* Cb = out + (size_t)(m0 + wm * 64) * N_DIM + n0 + wn * 64;
    #pragma unroll
    for (int t4 = 0; t4 < 4; t4++) {
        #pragma unroll
        for (int j = 0; j < 8; j++) {
            float* p0 = Cb + (size_t)(t4 * 16 + g) * N_DIM + j * 8 + tc * 2;
            float* p1 = p0 + 8 * N_DIM;
            *reinterpret_cast<float2*>(p0) = make_float2(acc[t4][j][0], acc[t4][j][1]);
            *reinterpret_cast<float2*>(p1) = make_float2(acc[t4][j][2], acc[t4][j][3]);
        }
    }
}

// ---------------------------------------------------------------------------
// Entry point. Inputs: x f32, grid_indices i32, scale f32, lut f32.
// Output: float32 [8192, 4096].
// ---------------------------------------------------------------------------
extern "C" void kernel_launch(void* const* d_in, const int* in_sizes, int n_in,
                              void* d_out, int out_size) {
    const float* x     = (const float*)d_in[0];
    const int*   idx   = (const int*)  d_in[1];
    const float* scale = (const float*)d_in[2];
    const float* lut   = (const float*)d_in[3];
    float* out = (float*)d_out;

    prep_kernel<<<PREP_BLOCKS, 256>>>(x, idx, scale, lut);

    cudaFuncSetAttribute(gemm_hmma_kernel,
                         cudaFuncAttributeMaxDynamicSharedMemorySize, SMEM_TOTAL);
    dim3 grid(N_DIM / BN, M_DIM / BM);   // 32 x 64
    gemm_hmma_kernel<<<grid, 128, SMEM_TOTAL>>>(out);
}

// round 8
// speedup vs baseline: 2.4180x; 1.0068x over previous
#include <cuda_runtime.h>
#include <cuda_fp16.h>
#include <cstdint>

// Problem dims (fixed by the dataset)
#define M_DIM 8192   // B*S
#define N_DIM 4096   // OUT_F
#define K_DIM 4096   // IN_F

// GEMM tiling: CTA 128x128, 4 warps (2m x 2n), warp tile 64x64
#define BM 128
#define BN 128
#define BK 64                      // 64 halves = 128B rows (SW128 atom)
#define NSTAGES 3
#define KSTEPS (K_DIM / BK)        // 64

#define A_STAGE_BYTES (BM * 128)   // 16 KB
#define B_STAGE_BYTES (BN * 128)   // 16 KB
#define STAGE_BYTES   (A_STAGE_BYTES + B_STAGE_BYTES)   // 32 KB
#define SMEM_TOTAL    (NSTAGES * STAGE_BYTES)           // 96 KB -> 2 CTAs/SM

// Persistent grid
#define NTILES_X (N_DIM / BN)      // 32
#define NTILES   ((M_DIM / BM) * NTILES_X)   // 2048
#define GRID_CTAS 304              // 152 SMs x 2 CTAs

// Scratch (no cudaMalloc allowed)
__device__ __half g_W[(size_t)N_DIM * K_DIM];   // 32 MB dequantized weights
__device__ __half g_X[(size_t)M_DIM * K_DIM];   // 64 MB fp16 activations

// ---------------------------------------------------------------------------
// helpers
// ---------------------------------------------------------------------------
static __device__ __forceinline__ uint32_t s2u(const void* p) {
    uint32_t a;
    asm("{ .reg .u64 t; cvta.to.shared.u64 t, %1; cvt.u32.u64 %0, t; }"
        : "=r"(a) : "l"(p));
    return a;
}

static __device__ __forceinline__ void cp_async16(uint32_t dst, const void* src) {
    asm volatile("cp.async.cg.shared.global [%0], [%1], 16;"
                 :: "r"(dst), "l"(src) : "memory");
}
#define CP_COMMIT() asm volatile("cp.async.commit_group;" ::: "memory")
#define CP_WAIT1()  asm volatile("cp.async.wait_group 1;" ::: "memory")

#define LDSM_X4(r0, r1, r2, r3, a) \
    asm volatile("ldmatrix.sync.aligned.m8n8.x4.shared.b16 {%0,%1,%2,%3}, [%4];" \
                 : "=r"(r0), "=r"(r1), "=r"(r2), "=r"(r3) : "r"(a))

static __device__ __forceinline__ void mma16816(float* c, const uint32_t* a,
                                                const uint32_t* b) {
    asm volatile(
        "mma.sync.aligned.m16n8k16.row.col.f32.f16.f16.f32 "
        "{%0,%1,%2,%3}, {%4,%5,%6,%7}, {%8,%9}, {%0,%1,%2,%3};"
        : "+f"(c[0]), "+f"(c[1]), "+f"(c[2]), "+f"(c[3])
        : "r"(a[0]), "r"(a[1]), "r"(a[2]), "r"(a[3]), "r"(b[0]), "r"(b[1]));
}

static __device__ __forceinline__ const char* a_tile_ptr(int T) {
    return (const char*)(g_X + (size_t)((T >> 5) * BM) * K_DIM);
}
static __device__ __forceinline__ const char* b_tile_ptr(int T) {
    return (const char*)(g_W + (size_t)((T & (NTILES_X - 1)) * BN) * K_DIM);
}

// ---------------------------------------------------------------------------
// Fused prep kernel: interleaved dequant (1/3 of blocks) + convert (2/3).
// Measured at ~92% of HBM spec — near roofline.
// ---------------------------------------------------------------------------
#define DEQ_BLOCKS  ((N_DIM * K_DIM) / (256 * 8))            // 8192
#define CVT_BLOCKS  (((size_t)M_DIM * K_DIM) / (256 * 8))    // 16384
#define PREP_BLOCKS (DEQ_BLOCKS + CVT_BLOCKS)                // 24576

__global__ void prep_kernel(const float* __restrict__ x,
                            const int* __restrict__ idx,
                            const float* __restrict__ scale,
                            const float* __restrict__ lut) {
    int b = blockIdx.x;
    int r3 = b % 3;
    if (r3 == 2) {
        int db = b / 3;
        size_t base = ((size_t)db * 256 + threadIdx.x) * 8;
        int row = (int)(base / K_DIM);
        float s = scale[row];
        int4 c0 = *reinterpret_cast<const int4*>(idx + base);
        int4 c1 = *reinterpret_cast<const int4*>(idx + base + 4);
        __half2 h[4];
        h[0] = __floats2half2_rn(lut[c0.x] * s, lut[c0.y] * s);
        h[1] = __floats2half2_rn(lut[c0.z] * s, lut[c0.w] * s);
        h[2] = __floats2half2_rn(lut[c1.x] * s, lut[c1.y] * s);
        h[3] = __floats2half2_rn(lut[c1.z] * s, lut[c1.w] * s);
        *reinterpret_cast<uint4*>(g_W + base) = *reinterpret_cast<uint4*>(h);
    } else {
        int cb = (b / 3) * 2 + r3;
        size_t base = ((size_t)cb * 256 + threadIdx.x) * 8;
        float4 v0 = *reinterpret_cast<const float4*>(x + base);
        float4 v1 = *reinterpret_cast<const float4*>(x + base + 4);
        __half2 h[4];
        h[0] = __floats2half2_rn(v0.x, v0.y);
        h[1] = __floats2half2_rn(v0.z, v0.w);
        h[2] = __floats2half2_rn(v1.x, v1.y);
        h[3] = __floats2half2_rn(v1.z, v1.w);
        *reinterpret_cast<uint4*>(g_X + base) = *reinterpret_cast<uint4*>(h);
    }
}

// ---------------------------------------------------------------------------
// Persistent HMMA GEMM. 304 CTAs loop over tiles; the cp.async ring runs
// CONTINUOUSLY across tile boundaries (ksteps 62/63 of tile t refill ksteps
// 0/1 of the CTA's next tile), so the epilogue overlaps the next tile's
// first ksteps — no per-tile drain/fill bubbles and no wave tail.
//   out[m,n] = sum_k X[m,k] * W[n,k]
// ---------------------------------------------------------------------------
__device__ __forceinline__ void load_half(int tid, uint32_t S, const char* Gk) {
    const size_t krow = (size_t)K_DIM * 2;   // row stride bytes
    #pragma unroll
    for (int j = 0; j < 8; j++) {
        int cid = tid + 128 * j;
        int row = cid >> 3;
        int c   = cid & 7;
        uint32_t sw = (uint32_t)(row * 128 + ((c ^ (row & 7)) * 16));
        cp_async16(S + sw, Gk + (size_t)row * krow + c * 16);
    }
}

__global__ void __launch_bounds__(128, 2)
gemm_hmma_kernel(float* __restrict__ out) {
    extern __shared__ __align__(1024) char smem[];
    const uint32_t sb = s2u(smem);
    const int tid = threadIdx.x;
    const int wid = tid >> 5;
    const int lid = tid & 31;
    const int wm = wid & 1;        // 0..1 : 64-row slab
    const int wn = wid >> 1;       // 0..1 : 64-col slab

    // per-lane ldmatrix address components (stage-relative, tile-invariant)
    uint32_t a_rowoff[4], b_rowoff[4];
    #pragma unroll
    for (int i = 0; i < 4; i++)
        a_rowoff[i] = (uint32_t)((wm * 64 + i * 16 + (lid & 15)) * 128);
    #pragma unroll
    for (int j2 = 0; j2 < 4; j2++)
        b_rowoff[j2] = (uint32_t)((wn * 64 + j2 * 16 + (lid & 7) +
                                   ((lid >> 4) & 1) * 8) * 128);
    uint32_t a_ch[4], b_ch[4];
    #pragma unroll
    for (int q = 0; q < 4; q++) {
        a_ch[q] = (uint32_t)((((2 * q + (lid >> 4)) ^ (lid & 7)) * 16));
        b_ch[q] = (uint32_t)((((2 * q + ((lid >> 3) & 1)) ^ (lid & 7)) * 16));
    }

    float acc[4][8][4];
    #pragma unroll
    for (int i = 0; i < 4; i++)
        #pragma unroll
        for (int j = 0; j < 8; j++)
            #pragma unroll
            for (int r = 0; r < 4; r++)
                acc[i][j][r] = 0.0f;

    const int T0 = blockIdx.x;

    // Prologue for first tile: fill stages 0..1 (ksteps 0,1)
    {
        const char* A0 = a_tile_ptr(T0);
        const char* B0 = b_tile_ptr(T0);
        load_half(tid, sb + 0 * STAGE_BYTES, A0);
        load_half(tid, sb + 0 * STAGE_BYTES + A_STAGE_BYTES, B0);
        CP_COMMIT();
        load_half(tid, sb + 1 * STAGE_BYTES, A0 + 128);
        load_half(tid, sb + 1 * STAGE_BYTES + A_STAGE_BYTES, B0 + 128);
        CP_COMMIT();
    }

    // refill source cursors (carry across tile boundaries)
    const char* rA = a_tile_ptr(T0) + 2 * 128;
    const char* rB = b_tile_ptr(T0) + 2 * 128;

    uint32_t a_frag[2][4][4];
    uint32_t b_frag[2][4][4];
    int s_cur = 0, s_nxt = 2;

    #pragma unroll 1
    for (int T = T0; T < NTILES; T += GRID_CTAS) {
        const bool has_next = (T + GRID_CTAS) < NTILES;
        const char* AgN = has_next ? a_tile_ptr(T + GRID_CTAS) : rA;
        const char* BgN = has_next ? b_tile_ptr(T + GRID_CTAS) : rB;
        bool live = true;

        #pragma unroll 1
        for (int i = 0; i < KSTEPS; i++) {
            CP_WAIT1();
            __syncthreads();

            const uint32_t SA = sb + s_cur * STAGE_BYTES;
            const uint32_t SB = SA + A_STAGE_BYTES;
            const uint32_t SNX = sb + s_nxt * STAGE_BYTES;

            // ksteps 62/63 refill the NEXT tile's ksteps 0/1
            if (i == KSTEPS - 2) { rA = AgN; rB = BgN; live = has_next; }

            // q0 fragment prefetch FIRST: start the MMA dependency chain
            #pragma unroll
            for (int t4 = 0; t4 < 4; t4++)
                LDSM_X4(a_frag[0][t4][0], a_frag[0][t4][1],
                        a_frag[0][t4][2], a_frag[0][t4][3],
                        SA + a_rowoff[t4] + a_ch[0]);
            #pragma unroll
            for (int j2 = 0; j2 < 4; j2++)
                LDSM_X4(b_frag[0][j2][0], b_frag[0][j2][1],
                        b_frag[0][j2][2], b_frag[0][j2][3],
                        SB + b_rowoff[j2] + b_ch[0]);

            // refill A-half: overlaps with first MMA block
            if (live) load_half(tid, SNX, rA);

            #pragma unroll
            for (int q = 0; q < 4; q++) {
                const int cur = q & 1, nxt = cur ^ 1;
                if (q < 3) {
                    #pragma unroll
                    for (int t4 = 0; t4 < 4; t4++)
                        LDSM_X4(a_frag[nxt][t4][0], a_frag[nxt][t4][1],
                                a_frag[nxt][t4][2], a_frag[nxt][t4][3],
                                SA + a_rowoff[t4] + a_ch[q + 1]);
                    #pragma unroll
                    for (int j2 = 0; j2 < 4; j2++)
                        LDSM_X4(b_frag[nxt][j2][0], b_frag[nxt][j2][1],
                                b_frag[nxt][j2][2], b_frag[nxt][j2][3],
                                SB + b_rowoff[j2] + b_ch[q + 1]);
                }
                if (q == 0) {
                    // refill B-half; ALWAYS commit (1 group/kstep accounting)
                    if (live) load_half(tid, SNX + A_STAGE_BYTES, rB);
                    CP_COMMIT();
                }
                #pragma unroll
                for (int t4 = 0; t4 < 4; t4++)
                    #pragma unroll
                    for (int j = 0; j < 8; j++)
                        mma16816(acc[t4][j], a_frag[cur][t4],
                                 &b_frag[cur][j >> 1][(j & 1) * 2]);
            }

            rA += 128;
            rB += 128;
            s_cur = (s_cur == NSTAGES - 1) ? 0 : s_cur + 1;
            s_nxt = (s_nxt == NSTAGES - 1) ? 0 : s_nxt + 1;
        }

        // Epilogue for tile T (no smem involved; overlaps next tile's loads)
        {
            const int m0 = (T >> 5) * BM;
            const int n0 = (T & (NTILES_X - 1)) * BN;
            const int g  = lid >> 2;
            const int tc = lid & 3;
            float* Cb = out + (size_t)(m0 + wm * 64) * N_DIM + n0 + wn * 64;
            #pragma unroll
            for (int t4 = 0; t4 < 4; t4++) {
                #pragma unroll
                for (int j = 0; j < 8; j++) {
                    float* p0 = Cb + (size_t)(t4 * 16 + g) * N_DIM + j * 8 + tc * 2;
                    float* p1 = p0 + 8 * N_DIM;
                    *reinterpret_cast<float2*>(p0) =
                        make_float2(acc[t4][j][0], acc[t4][j][1]);
                    *reinterpret_cast<float2*>(p1) =
                        make_float2(acc[t4][j][2], acc[t4][j][3]);
                    acc[t4][j][0] = 0.0f; acc[t4][j][1] = 0.0f;
                    acc[t4][j][2] = 0.0f; acc[t4][j][3] = 0.0f;
                }
            }
        }
    }
}

// ---------------------------------------------------------------------------
// Entry point. Inputs: x f32, grid_indices i32, scale f32, lut f32.
// Output: float32 [8192, 4096].
// ---------------------------------------------------------------------------
extern "C" void kernel_launch(void* const* d_in, const int* in_sizes, int n_in,
                              void* d_out, int out_size) {
    const float* x     = (const float*)d_in[0];
    const int*   idx   = (const int*)  d_in[1];
    const float* scale = (const float*)d_in[2];
    const float* lut   = (const float*)d_in[3];
    float* out = (float*)d_out;

    prep_kernel<<<PREP_BLOCKS, 256>>>(x, idx, scale, lut);

    cudaFuncSetAttribute(gemm_hmma_kernel,
                         cudaFuncAttributeMaxDynamicSharedMemorySize, SMEM_TOTAL);
    gemm_hmma_kernel<<<GRID_CTAS, 128, SMEM_TOTAL>>>(out);
}

// round 9
// speedup vs baseline: 2.4185x; 1.0002x over previous
#include <cuda_runtime.h>
#include <cuda_fp16.h>
#include <cstdint>

// Problem dims (fixed by the dataset)
#define M_DIM 8192   // B*S
#define N_DIM 4096   // OUT_F
#define K_DIM 4096   // IN_F

// GEMM tiling: CTA 128x128, 4 warps (2m x 2n), warp tile 64x64
#define BM 128
#define BN 128
#define BK 64                      // 64 halves = 128B rows (SW128 atom)
#define KSTEPS (K_DIM / BK)        // 64

// Asymmetric stage rings: A 3-deep, B 4-deep (separate commit groups,
// wait_group 3 => A has ~2-kstep slack, B ~3-kstep slack)
#define A_ST 16384                 // 128 rows x 128B
#define B_ST 16384
#define A_RING 3
#define B_RING 4
#define B_BASE (A_RING * A_ST)     // 49152
#define SMEM_TOTAL (A_RING * A_ST + B_RING * B_ST)   // 114688 = 112KB -> 2 CTAs/SM

// Persistent grid
#define NTILES_X (N_DIM / BN)      // 32
#define NTILES   ((M_DIM / BM) * NTILES_X)   // 2048
#define GRID_CTAS 304              // 152 SMs x 2 CTAs

// Scratch (no cudaMalloc allowed)
__device__ __half g_W[(size_t)N_DIM * K_DIM];   // 32 MB dequantized weights
__device__ __half g_X[(size_t)M_DIM * K_DIM];   // 64 MB fp16 activations

// ---------------------------------------------------------------------------
// helpers
// ---------------------------------------------------------------------------
static __device__ __forceinline__ uint32_t s2u(const void* p) {
    uint32_t a;
    asm("{ .reg .u64 t; cvta.to.shared.u64 t, %1; cvt.u32.u64 %0, t; }"
        : "=r"(a) : "l"(p));
    return a;
}

static __device__ __forceinline__ void cp_async16(uint32_t dst, const void* src) {
    asm volatile("cp.async.cg.shared.global [%0], [%1], 16;"
                 :: "r"(dst), "l"(src) : "memory");
}
#define CP_COMMIT() asm volatile("cp.async.commit_group;" ::: "memory")
#define CP_WAIT3()  asm volatile("cp.async.wait_group 3;" ::: "memory")

#define LDSM_X4(r0, r1, r2, r3, a) \
    asm volatile("ldmatrix.sync.aligned.m8n8.x4.shared.b16 {%0,%1,%2,%3}, [%4];" \
                 : "=r"(r0), "=r"(r1), "=r"(r2), "=r"(r3) : "r"(a))

static __device__ __forceinline__ void mma16816(float* c, const uint32_t* a,
                                                const uint32_t* b) {
    asm volatile(
        "mma.sync.aligned.m16n8k16.row.col.f32.f16.f16.f32 "
        "{%0,%1,%2,%3}, {%4,%5,%6,%7}, {%8,%9}, {%0,%1,%2,%3};"
        : "+f"(c[0]), "+f"(c[1]), "+f"(c[2]), "+f"(c[3])
        : "r"(a[0]), "r"(a[1]), "r"(a[2]), "r"(a[3]), "r"(b[0]), "r"(b[1]));
}

static __device__ __forceinline__ const char* a_tile_ptr(int T) {
    return (const char*)(g_X + (size_t)((T >> 5) * BM) * K_DIM);
}
static __device__ __forceinline__ const char* b_tile_ptr(int T) {
    return (const char*)(g_W + (size_t)((T & (NTILES_X - 1)) * BN) * K_DIM);
}

// ---------------------------------------------------------------------------
// Fused prep kernel: interleaved dequant (1/3 of blocks) + convert (2/3).
// Measured ~92% of HBM spec — near roofline; unchanged.
// ---------------------------------------------------------------------------
#define DEQ_BLOCKS  ((N_DIM * K_DIM) / (256 * 8))            // 8192
#define CVT_BLOCKS  (((size_t)M_DIM * K_DIM) / (256 * 8))    // 16384
#define PREP_BLOCKS (DEQ_BLOCKS + CVT_BLOCKS)                // 24576

__global__ void prep_kernel(const float* __restrict__ x,
                            const int* __restrict__ idx,
                            const float* __restrict__ scale,
                            const float* __restrict__ lut) {
    int b = blockIdx.x;
    int r3 = b % 3;
    if (r3 == 2) {
        int db = b / 3;
        size_t base = ((size_t)db * 256 + threadIdx.x) * 8;
        int row = (int)(base / K_DIM);
        float s = scale[row];
        int4 c0 = *reinterpret_cast<const int4*>(idx + base);
        int4 c1 = *reinterpret_cast<const int4*>(idx + base + 4);
        __half2 h[4];
        h[0] = __floats2half2_rn(lut[c0.x] * s, lut[c0.y] * s);
        h[1] = __floats2half2_rn(lut[c0.z] * s, lut[c0.w] * s);
        h[2] = __floats2half2_rn(lut[c1.x] * s, lut[c1.y] * s);
        h[3] = __floats2half2_rn(lut[c1.z] * s, lut[c1.w] * s);
        *reinterpret_cast<uint4*>(g_W + base) = *reinterpret_cast<uint4*>(h);
    } else {
        int cb = (b / 3) * 2 + r3;
        size_t base = ((size_t)cb * 256 + threadIdx.x) * 8;
        float4 v0 = *reinterpret_cast<const float4*>(x + base);
        float4 v1 = *reinterpret_cast<const float4*>(x + base + 4);
        __half2 h[4];
        h[0] = __floats2half2_rn(v0.x, v0.y);
        h[1] = __floats2half2_rn(v0.z, v0.w);
        h[2] = __floats2half2_rn(v1.x, v1.y);
        h[3] = __floats2half2_rn(v1.z, v1.w);
        *reinterpret_cast<uint4*>(g_X + base) = *reinterpret_cast<uint4*>(h);
    }
}

// ---------------------------------------------------------------------------
// Persistent HMMA GEMM with asymmetric A(3)/B(4) cp.async rings.
// Per kstep i: commit group {A-refill for kstep i+2}, then {B-refill for
// kstep i+3}. wait_group 3 at the kstep head guarantees A(i),B(i) complete
// while leaving ~2/3-kstep in-flight slack. Rings run continuously across
// tile boundaries (persistent CTAs, epilogue overlapped).
//   out[m,n] = sum_k X[m,k] * W[n,k]
// ---------------------------------------------------------------------------
__device__ __forceinline__ void load_half(int tid, uint32_t S, const char* Gk) {
    const size_t krow = (size_t)K_DIM * 2;   // row stride bytes
    #pragma unroll
    for (int j = 0; j < 8; j++) {
        int cid = tid + 128 * j;
        int row = cid >> 3;
        int c   = cid & 7;
        uint32_t sw = (uint32_t)(row * 128 + ((c ^ (row & 7)) * 16));
        cp_async16(S + sw, Gk + (size_t)row * krow + c * 16);
    }
}

__global__ void __launch_bounds__(128, 2)
gemm_hmma_kernel(float* __restrict__ out) {
    extern __shared__ __align__(1024) char smem[];
    const uint32_t sb  = s2u(smem);
    const uint32_t sbB = sb + B_BASE;
    const int tid = threadIdx.x;
    const int wid = tid >> 5;
    const int lid = tid & 31;
    const int wm = wid & 1;        // 0..1 : 64-row slab
    const int wn = wid >> 1;       // 0..1 : 64-col slab

    // per-lane ldmatrix address components (stage-relative, tile-invariant)
    uint32_t a_rowoff[4], b_rowoff[4];
    #pragma unroll
    for (int i = 0; i < 4; i++)
        a_rowoff[i] = (uint32_t)((wm * 64 + i * 16 + (lid & 15)) * 128);
    #pragma unroll
    for (int j2 = 0; j2 < 4; j2++)
        b_rowoff[j2] = (uint32_t)((wn * 64 + j2 * 16 + (lid & 7) +
                                   ((lid >> 4) & 1) * 8) * 128);
    uint32_t a_ch[4], b_ch[4];
    #pragma unroll
    for (int q = 0; q < 4; q++) {
        a_ch[q] = (uint32_t)((((2 * q + (lid >> 4)) ^ (lid & 7)) * 16));
        b_ch[q] = (uint32_t)((((2 * q + ((lid >> 3) & 1)) ^ (lid & 7)) * 16));
    }

    float acc[4][8][4];
    #pragma unroll
    for (int i = 0; i < 4; i++)
        #pragma unroll
        for (int j = 0; j < 8; j++)
            #pragma unroll
            for (int r = 0; r < 4; r++)
                acc[i][j][r] = 0.0f;

    const int T0 = blockIdx.x;

    // Prologue: A ksteps 0,1 and B ksteps 0,1,2; commit order [A0,B0,A1,B1,B2]
    {
        const char* A0 = a_tile_ptr(T0);
        const char* B0 = b_tile_ptr(T0);
        load_half(tid, sb  + 0 * A_ST, A0);          CP_COMMIT();
        load_half(tid, sbB + 0 * B_ST, B0);          CP_COMMIT();
        load_half(tid, sb  + 1 * A_ST, A0 + 128);    CP_COMMIT();
        load_half(tid, sbB + 1 * B_ST, B0 + 128);    CP_COMMIT();
        load_half(tid, sbB + 2 * B_ST, B0 + 256);    CP_COMMIT();
    }

    // refill source cursors (carry across tile boundaries)
    const char* rA = a_tile_ptr(T0) + 2 * 128;   // next A kstep to fill: 2
    const char* rB = b_tile_ptr(T0) + 3 * 128;   // next B kstep to fill: 3
    bool liveA = true, liveB = true;

    uint32_t a_frag[2][4][4];
    uint32_t b_frag[2][4][4];
    int sA_cur = 0, sA_nxt = 2;    // mod 3
    int sB_cur = 0, sB_nxt = 3;    // mod 4

    #pragma unroll 1
    for (int T = T0; T < NTILES; T += GRID_CTAS) {
        const bool has_next = (T + GRID_CTAS) < NTILES;
        const char* AgN = has_next ? a_tile_ptr(T + GRID_CTAS) : rA;
        const char* BgN = has_next ? b_tile_ptr(T + GRID_CTAS) : rB;

        #pragma unroll 1
        for (int i = 0; i < KSTEPS; i++) {
            CP_WAIT3();
            __syncthreads();

            const uint32_t SA  = sb  + sA_cur * A_ST;
            const uint32_t SB  = sbB + sB_cur * B_ST;
            const uint32_t SAX = sb  + sA_nxt * A_ST;
            const uint32_t SBX = sbB + sB_nxt * B_ST;

            // ring cursors wrap to the NEXT tile at their lookahead horizon
            if (i == KSTEPS - 2) { rA = AgN; liveA = has_next; }   // A(i+2)
            if (i == KSTEPS - 3) { rB = BgN; liveB = has_next; }   // B(i+3)

            // q0 fragment prefetch FIRST: start the MMA dependency chain
            #pragma unroll
            for (int t4 = 0; t4 < 4; t4++)
                LDSM_X4(a_frag[0][t4][0], a_frag[0][t4][1],
                        a_frag[0][t4][2], a_frag[0][t4][3],
                        SA + a_rowoff[t4] + a_ch[0]);
            #pragma unroll
            for (int j2 = 0; j2 < 4; j2++)
                LDSM_X4(b_frag[0][j2][0], b_frag[0][j2][1],
                        b_frag[0][j2][2], b_frag[0][j2][3],
                        SB + b_rowoff[j2] + b_ch[0]);

            // A-refill group (for kstep i+2); ALWAYS commit for accounting
            if (liveA) load_half(tid, SAX, rA);
            CP_COMMIT();

            #pragma unroll
            for (int q = 0; q < 4; q++) {
                const int cur = q & 1, nxt = cur ^ 1;
                if (q < 3) {
                    #pragma unroll
                    for (int t4 = 0; t4 < 4; t4++)
                        LDSM_X4(a_frag[nxt][t4][0], a_frag[nxt][t4][1],
                                a_frag[nxt][t4][2], a_frag[nxt][t4][3],
                                SA + a_rowoff[t4] + a_ch[q + 1]);
                    #pragma unroll
                    for (int j2 = 0; j2 < 4; j2++)
                        LDSM_X4(b_frag[nxt][j2][0], b_frag[nxt][j2][1],
                                b_frag[nxt][j2][2], b_frag[nxt][j2][3],
                                SB + b_rowoff[j2] + b_ch[q + 1]);
                }
                if (q == 0) {
                    // B-refill group (for kstep i+3); ALWAYS commit
                    if (liveB) load_half(tid, SBX, rB);
                    CP_COMMIT();
                }
                #pragma unroll
                for (int t4 = 0; t4 < 4; t4++)
                    #pragma unroll
                    for (int j = 0; j < 8; j++)
                        mma16816(acc[t4][j], a_frag[cur][t4],
                                 &b_frag[cur][j >> 1][(j & 1) * 2]);
            }

            rA += 128;
            rB += 128;
            sA_cur = (sA_cur == A_RING - 1) ? 0 : sA_cur + 1;
            sA_nxt = (sA_nxt == A_RING - 1) ? 0 : sA_nxt + 1;
            sB_cur = (sB_cur == B_RING - 1) ? 0 : sB_cur + 1;
            sB_nxt = (sB_nxt == B_RING - 1) ? 0 : sB_nxt + 1;
        }

        // Epilogue for tile T (no smem; overlaps the next tile's in-flight loads)
        {
            const int m0 = (T >> 5) * BM;
            const int n0 = (T & (NTILES_X - 1)) * BN;
            const int g  = lid >> 2;
            const int tc = lid & 3;
            float* Cb = out + (size_t)(m0 + wm * 64) * N_DIM + n0 + wn * 64;
            #pragma unroll
            for (int t4 = 0; t4 < 4; t4++) {
                #pragma unroll
                for (int j = 0; j < 8; j++) {
                    float* p0 = Cb + (size_t)(t4 * 16 + g) * N_DIM + j * 8 + tc * 2;
                    float* p1 = p0 + 8 * N_DIM;
                    *reinterpret_cast<float2*>(p0) =
                        make_float2(acc[t4][j][0], acc[t4][j][1]);
                    *reinterpret_cast<float2*>(p1) =
                        make_float2(acc[t4][j][2], acc[t4][j][3]);
                    acc[t4][j][0] = 0.0f; acc[t4][j][1] = 0.0f;
                    acc[t4][j][2] = 0.0f; acc[t4][j][3] = 0.0f;
                }
            }
        }
    }
}

// ---------------------------------------------------------------------------
// Entry point. Inputs: x f32, grid_indices i32, scale f32, lut f32.
// Output: float32 [8192, 4096].
// ---------------------------------------------------------------------------
extern "C" void kernel_launch(void* const* d_in, const int* in_sizes, int n_in,
                              void* d_out, int out_size) {
    const float* x     = (const float*)d_in[0];
    const int*   idx   = (const int*)  d_in[1];
    const float* scale = (const float*)d_in[2];
    const float* lut   = (const float*)d_in[3];
    float* out = (float*)d_out;

    prep_kernel<<<PREP_BLOCKS, 256>>>(x, idx, scale, lut);

    cudaFuncSetAttribute(gemm_hmma_kernel,
                         cudaFuncAttributeMaxDynamicSharedMemorySize, SMEM_TOTAL);
    gemm_hmma_kernel<<<GRID_CTAS, 128, SMEM_TOTAL>>>(out);
}